// round 1
// baseline (speedup 1.0000x reference)
#include <cuda_runtime.h>
#include <math.h>

#define BATCH  4
#define SEQ    2048
#define DMODEL 1024
#define NH     16
#define HD     64
#define NTOK   (BATCH*SEQ)

// Scratch (static device globals: allowed; runtime allocs are not)
__device__ float g_q[(size_t)BATCH*NH*SEQ*HD];     // [b,h,s,dk]
__device__ float g_k[(size_t)BATCH*NH*SEQ*HD];
__device__ float g_v[(size_t)BATCH*NH*SEQ*HD];
__device__ float g_attn[(size_t)NTOK*DMODEL];      // [b,s,h*HD+dk] row-major

// ---------------------------------------------------------------------------
// SGEMM: C = A @ W^T   (A: [M=8192, K=1024] row-major, W: [N=1024, K=1024] row-major)
// headmode=1 -> scatter output into [b,h,s,dk]; headmode=0 -> plain row-major
// ---------------------------------------------------------------------------
#define BM 128
#define BN 128
#define BK 16
#define BPAD 132

__global__ void __launch_bounds__(256, 2)
sgemm_nt(const float* __restrict__ A, const float* __restrict__ W,
         float* __restrict__ C, int headmode)
{
    __shared__ float As[BK][BPAD];
    __shared__ float Bs[BK][BPAD];

    const int tid = threadIdx.x;
    const int bm  = blockIdx.y * BM;
    const int bn  = blockIdx.x * BN;
    const int tx  = tid & 15;
    const int ty  = tid >> 4;

    float acc[8][8] = {};

    for (int k0 = 0; k0 < DMODEL; k0 += BK) {
        #pragma unroll
        for (int l = 0; l < 2; l++) {
            int idx = tid + l * 256;            // 0..511 float4 slots
            int r   = idx >> 2;                 // 0..127
            int cv  = (idx & 3) * 4;            // 0,4,8,12
            float4 va = *reinterpret_cast<const float4*>(
                &A[(size_t)(bm + r) * DMODEL + k0 + cv]);
            As[cv + 0][r] = va.x; As[cv + 1][r] = va.y;
            As[cv + 2][r] = va.z; As[cv + 3][r] = va.w;
            float4 vb = *reinterpret_cast<const float4*>(
                &W[(size_t)(bn + r) * DMODEL + k0 + cv]);
            Bs[cv + 0][r] = vb.x; Bs[cv + 1][r] = vb.y;
            Bs[cv + 2][r] = vb.z; Bs[cv + 3][r] = vb.w;
        }
        __syncthreads();

        #pragma unroll
        for (int kk = 0; kk < BK; kk++) {
            float a[8], b[8];
            *reinterpret_cast<float4*>(&a[0]) = *reinterpret_cast<float4*>(&As[kk][ty * 8]);
            *reinterpret_cast<float4*>(&a[4]) = *reinterpret_cast<float4*>(&As[kk][ty * 8 + 4]);
            *reinterpret_cast<float4*>(&b[0]) = *reinterpret_cast<float4*>(&Bs[kk][tx * 8]);
            *reinterpret_cast<float4*>(&b[4]) = *reinterpret_cast<float4*>(&Bs[kk][tx * 8 + 4]);
            #pragma unroll
            for (int i = 0; i < 8; i++)
                #pragma unroll
                for (int j = 0; j < 8; j++)
                    acc[i][j] = fmaf(a[i], b[j], acc[i][j]);
        }
        __syncthreads();
    }

    #pragma unroll
    for (int i = 0; i < 8; i++) {
        int m  = bm + ty * 8 + i;
        int o0 = bn + tx * 8;
        size_t base;
        if (headmode) {
            int bb = m >> 11;       // / SEQ
            int s  = m & (SEQ - 1);
            int h  = o0 >> 6;       // / HD
            int dk = o0 & (HD - 1);
            base = ((size_t)(bb * NH + h) * SEQ + s) * HD + dk;
        } else {
            base = (size_t)m * DMODEL + o0;
        }
        *reinterpret_cast<float4*>(&C[base]) =
            make_float4(acc[i][0], acc[i][1], acc[i][2], acc[i][3]);
        *reinterpret_cast<float4*>(&C[base + 4]) =
            make_float4(acc[i][4], acc[i][5], acc[i][6], acc[i][7]);
    }
}

// ---------------------------------------------------------------------------
// Flash attention forward, fp32, causal. Br=Bc=64, 256 threads, 4x4/thread.
// Output written directly in [b, s, h*HD+dk] layout (ready for final GEMM).
// ---------------------------------------------------------------------------
#define PITCH 68
#define FLASH_SMEM (4 * 64 * PITCH * 4)   // 69632 bytes

__global__ void __launch_bounds__(256)
flash_fwd(const float* __restrict__ Q, const float* __restrict__ K,
          const float* __restrict__ V, float* __restrict__ O)
{
    extern __shared__ float sm[];
    float* sQT = sm;                    // [d][r], pitch 68 (Q transposed, pre-scaled)
    float* sKT = sm + 64 * PITCH;       // [d][c], pitch 68 (K transposed)
    float* sV  = sm + 2 * 64 * PITCH;   // [key][dk], pitch 68
    float* sP  = sm + 3 * 64 * PITCH;   // [r][d], pitch 68

    const int qt  = gridDim.x - 1 - blockIdx.x;  // long CTAs scheduled first
    const int bh  = blockIdx.y;
    const int tid = threadIdx.x;
    const int tx  = tid & 15;
    const int ty  = tid >> 4;

    const float* Qh = Q + (size_t)bh * SEQ * HD;
    const float* Kh = K + (size_t)bh * SEQ * HD;
    const float* Vh = V + (size_t)bh * SEQ * HD;

    // Load Q tile transposed, pre-scaled by 1/sqrt(DK) = 0.125
    #pragma unroll
    for (int l = 0; l < 4; l++) {
        int fi = l * 256 + tid;
        int r  = fi >> 4;
        int v4 = (fi & 15) * 4;
        float4 x = *reinterpret_cast<const float4*>(
            &Qh[(size_t)(qt * 64 + r) * HD + v4]);
        sQT[(v4 + 0) * PITCH + r] = x.x * 0.125f;
        sQT[(v4 + 1) * PITCH + r] = x.y * 0.125f;
        sQT[(v4 + 2) * PITCH + r] = x.z * 0.125f;
        sQT[(v4 + 3) * PITCH + r] = x.w * 0.125f;
    }

    float o[4][4] = {};
    float mrow[4] = {-1e30f, -1e30f, -1e30f, -1e30f};
    float lrow[4] = {};

    for (int kt = 0; kt <= qt; kt++) {
        __syncthreads();   // prior PV done (and Q load on first iter)

        // Load K (transposed) and V tiles
        #pragma unroll
        for (int l = 0; l < 4; l++) {
            int fi = l * 256 + tid;
            int r  = fi >> 4;
            int v4 = (fi & 15) * 4;
            float4 kx = *reinterpret_cast<const float4*>(
                &Kh[(size_t)(kt * 64 + r) * HD + v4]);
            sKT[(v4 + 0) * PITCH + r] = kx.x;
            sKT[(v4 + 1) * PITCH + r] = kx.y;
            sKT[(v4 + 2) * PITCH + r] = kx.z;
            sKT[(v4 + 3) * PITCH + r] = kx.w;
            float4 vx = *reinterpret_cast<const float4*>(
                &Vh[(size_t)(kt * 64 + r) * HD + v4]);
            *reinterpret_cast<float4*>(&sV[r * PITCH + v4]) = vx;
        }
        __syncthreads();

        // S = (Q*scale) @ K^T
        float s[4][4] = {};
        #pragma unroll 8
        for (int d = 0; d < 64; d++) {
            float4 aq = *reinterpret_cast<float4*>(&sQT[d * PITCH + ty * 4]);
            float4 bk = *reinterpret_cast<float4*>(&sKT[d * PITCH + tx * 4]);
            float a[4] = {aq.x, aq.y, aq.z, aq.w};
            float b[4] = {bk.x, bk.y, bk.z, bk.w};
            #pragma unroll
            for (int i = 0; i < 4; i++)
                #pragma unroll
                for (int j = 0; j < 4; j++)
                    s[i][j] = fmaf(a[i], b[j], s[i][j]);
        }

        // Causal mask on the diagonal tile
        if (kt == qt) {
            #pragma unroll
            for (int i = 0; i < 4; i++)
                #pragma unroll
                for (int j = 0; j < 4; j++)
                    if (tx * 4 + j > ty * 4 + i) s[i][j] = -1e30f;
        }

        // Online softmax (16-lane row groups: lanes differ only in tx -> xor 8..1)
        #pragma unroll
        for (int i = 0; i < 4; i++) {
            float mx = fmaxf(fmaxf(s[i][0], s[i][1]), fmaxf(s[i][2], s[i][3]));
            #pragma unroll
            for (int off = 8; off; off >>= 1)
                mx = fmaxf(mx, __shfl_xor_sync(0xffffffffu, mx, off));
            float mnew = fmaxf(mrow[i], mx);
            float corr = __expf(mrow[i] - mnew);
            float rs = 0.f;
            #pragma unroll
            for (int j = 0; j < 4; j++) {
                float p = __expf(s[i][j] - mnew);
                s[i][j] = p;
                rs += p;
            }
            #pragma unroll
            for (int off = 8; off; off >>= 1)
                rs += __shfl_xor_sync(0xffffffffu, rs, off);
            lrow[i] = lrow[i] * corr + rs;
            mrow[i] = mnew;
            #pragma unroll
            for (int j = 0; j < 4; j++) o[i][j] *= corr;
            *reinterpret_cast<float4*>(&sP[(ty * 4 + i) * PITCH + tx * 4]) =
                make_float4(s[i][0], s[i][1], s[i][2], s[i][3]);
        }
        __syncthreads();

        // O += P @ V
        #pragma unroll 8
        for (int d = 0; d < 64; d++) {
            float4 bv = *reinterpret_cast<float4*>(&sV[d * PITCH + tx * 4]);
            #pragma unroll
            for (int i = 0; i < 4; i++) {
                float a = sP[(ty * 4 + i) * PITCH + d];
                o[i][0] = fmaf(a, bv.x, o[i][0]);
                o[i][1] = fmaf(a, bv.y, o[i][1]);
                o[i][2] = fmaf(a, bv.z, o[i][2]);
                o[i][3] = fmaf(a, bv.w, o[i][3]);
            }
        }
    }

    // Epilogue: normalize and write to [b, s, h*HD+dk]
    const int b = bh >> 4;      // / NH
    const int h = bh & 15;
    #pragma unroll
    for (int i = 0; i < 4; i++) {
        float inv  = 1.0f / lrow[i];
        int   qrow = qt * 64 + ty * 4 + i;
        size_t base = ((size_t)(b * SEQ + qrow)) * DMODEL + h * HD + tx * 4;
        *reinterpret_cast<float4*>(&O[base]) =
            make_float4(o[i][0] * inv, o[i][1] * inv, o[i][2] * inv, o[i][3] * inv);
    }
}

// ---------------------------------------------------------------------------
extern "C" void kernel_launch(void* const* d_in, const int* in_sizes, int n_in,
                              void* d_out, int out_size)
{
    const float* x  = (const float*)d_in[0];
    const float* wq = (const float*)d_in[1];
    const float* wk = (const float*)d_in[2];
    const float* wv = (const float*)d_in[3];
    const float* wo = (const float*)d_in[4];
    float* out = (float*)d_out;

    float *q, *k, *v, *attn;
    cudaGetSymbolAddress((void**)&q,    g_q);
    cudaGetSymbolAddress((void**)&k,    g_k);
    cudaGetSymbolAddress((void**)&v,    g_v);
    cudaGetSymbolAddress((void**)&attn, g_attn);

    cudaFuncSetAttribute(flash_fwd,
                         cudaFuncAttributeMaxDynamicSharedMemorySize, FLASH_SMEM);

    dim3 gg(DMODEL / BN, NTOK / BM);   // (8, 64)
    sgemm_nt<<<gg, 256>>>(x, wq, q, 1);
    sgemm_nt<<<gg, 256>>>(x, wk, k, 1);
    sgemm_nt<<<gg, 256>>>(x, wv, v, 1);

    flash_fwd<<<dim3(SEQ / 64, BATCH * NH), 256, FLASH_SMEM>>>(q, k, v, attn);

    sgemm_nt<<<gg, 256>>>(attn, wo, out, 0);
}

// round 3
// speedup vs baseline: 1.6390x; 1.6390x over previous
#include <cuda_runtime.h>
#include <cuda_bf16.h>
#include <cstdint>
#include <math.h>

#define BATCH  4
#define SEQ    2048
#define DMODEL 1024
#define NH     16
#define HD     64
#define NTOK   (BATCH*SEQ)

// ---------------- scratch (static device globals) ----------------
__device__ __align__(16) float g_q[(size_t)BATCH*NH*SEQ*HD];
__device__ __align__(16) float g_k[(size_t)BATCH*NH*SEQ*HD];
__device__ __align__(16) float g_v[(size_t)BATCH*NH*SEQ*HD];
__device__ __align__(16) float g_attn[(size_t)NTOK*DMODEL];
__device__ __align__(16) __nv_bfloat16 g_xh[(size_t)NTOK*DMODEL];
__device__ __align__(16) __nv_bfloat16 g_xl[(size_t)NTOK*DMODEL];
__device__ __align__(16) __nv_bfloat16 g_wh[(size_t)DMODEL*DMODEL];
__device__ __align__(16) __nv_bfloat16 g_wl[(size_t)DMODEL*DMODEL];

__device__ __forceinline__ uint32_t smem_u32(const void* p) {
    uint32_t a;
    asm("{ .reg .u64 t; cvta.to.shared.u64 t, %1; cvt.u32.u64 %0, t; }" : "=r"(a) : "l"(p));
    return a;
}

// ---------------------------------------------------------------------------
// fp32 -> bf16 hi/lo split (x = hi + lo)
// ---------------------------------------------------------------------------
__global__ void __launch_bounds__(256)
split_bf16(const float* __restrict__ src, __nv_bfloat16* __restrict__ hi,
           __nv_bfloat16* __restrict__ lo, int n4)
{
    int i = blockIdx.x * 256 + threadIdx.x;
    if (i >= n4) return;
    float4 x = reinterpret_cast<const float4*>(src)[i];
    __nv_bfloat16 h0 = __float2bfloat16(x.x), h1 = __float2bfloat16(x.y);
    __nv_bfloat16 h2 = __float2bfloat16(x.z), h3 = __float2bfloat16(x.w);
    __nv_bfloat16 l0 = __float2bfloat16(x.x - __bfloat162float(h0));
    __nv_bfloat16 l1 = __float2bfloat16(x.y - __bfloat162float(h1));
    __nv_bfloat16 l2 = __float2bfloat16(x.z - __bfloat162float(h2));
    __nv_bfloat16 l3 = __float2bfloat16(x.w - __bfloat162float(h3));
    reinterpret_cast<__nv_bfloat162*>(hi)[2*i]   = __halves2bfloat162(h0, h1);
    reinterpret_cast<__nv_bfloat162*>(hi)[2*i+1] = __halves2bfloat162(h2, h3);
    reinterpret_cast<__nv_bfloat162*>(lo)[2*i]   = __halves2bfloat162(l0, l1);
    reinterpret_cast<__nv_bfloat162*>(lo)[2*i+1] = __halves2bfloat162(l2, l3);
}

// ---------------------------------------------------------------------------
// HMMA GEMM: C[8192,1024] = Ah@Bh^T + Ah@Bl^T + Al@Bh^T
// CTA 128x128, BK=64 bf16, cp.async double buffer, mma.sync m16n8k16.
// ---------------------------------------------------------------------------
#define STAGE_BYTES 32768          // A(16K) + B(16K) per stage
#define GEMM_SMEM   (2*STAGE_BYTES)

__device__ __forceinline__ void gemm_issue(
    const __nv_bfloat16* __restrict__ As, const __nv_bfloat16* __restrict__ Bs,
    uint32_t sA, uint32_t sB, int bm0, int bn0, int k0, int tid)
{
    #pragma unroll
    for (int j = 0; j < 4; j++) {
        int id = tid + j * 256;            // 0..1023 16B-chunks per tile
        int r  = id >> 3;
        int c  = id & 7;
        uint32_t dsw = (uint32_t)(r * 128 + ((c ^ (r & 7)) * 16));
        const void* ga = As + (size_t)(bm0 + r) * DMODEL + k0 + c * 8;
        asm volatile("cp.async.cg.shared.global [%0], [%1], 16;" :: "r"(sA + dsw), "l"(ga));
        const void* gb = Bs + (size_t)(bn0 + r) * DMODEL + k0 + c * 8;
        asm volatile("cp.async.cg.shared.global [%0], [%1], 16;" :: "r"(sB + dsw), "l"(gb));
    }
    asm volatile("cp.async.commit_group;" ::: "memory");
}

__global__ void __launch_bounds__(256)
gemm_hmma_x3(const __nv_bfloat16* __restrict__ Ah, const __nv_bfloat16* __restrict__ Al,
             const __nv_bfloat16* __restrict__ Bh, const __nv_bfloat16* __restrict__ Bl,
             float* __restrict__ C, int headmode)
{
    extern __shared__ char smem[];
    const uint32_t sb = smem_u32(smem);
    const int tid  = threadIdx.x;
    const int wid  = tid >> 5;
    const int lane = tid & 31;
    const int wm   = (wid & 3) * 32;     // warp row origin in CTA tile
    const int wn   = (wid >> 2) * 64;    // warp col origin
    const int bm0  = blockIdx.y * 128;
    const int bn0  = blockIdx.x * 128;

    float acc[2][8][4] = {};

    // iteration -> (pass, k0):  pass 0: Ah*Bh, 1: Ah*Bl, 2: Al*Bh
    {
        gemm_issue(Ah, Bh, sb, sb + 16384, bm0, bn0, 0, tid);
    }

    #pragma unroll 1
    for (int it = 0; it < 48; it++) {
        const int cur = it & 1;
        if (it + 1 < 48) {
            int itn = it + 1;
            int p   = itn >> 4;
            int k0  = (itn & 15) * 64;
            const __nv_bfloat16* As = (p < 2) ? Ah : Al;
            const __nv_bfloat16* Bs = (p == 1) ? Bl : Bh;
            uint32_t sA = sb + (1 - cur) * STAGE_BYTES;
            gemm_issue(As, Bs, sA, sA + 16384, bm0, bn0, k0, tid);
            asm volatile("cp.async.wait_group 1;" ::: "memory");
        } else {
            asm volatile("cp.async.wait_group 0;" ::: "memory");
        }
        __syncthreads();

        const uint32_t sA = sb + cur * STAGE_BYTES;
        const uint32_t sB = sA + 16384;

        #pragma unroll
        for (int kk = 0; kk < 4; kk++) {
            uint32_t a[2][4];
            #pragma unroll
            for (int mi = 0; mi < 2; mi++) {
                int row = wm + mi * 16 + (lane & 15);
                int c   = kk * 2 + (lane >> 4);
                uint32_t addr = sA + row * 128 + ((c ^ (row & 7)) * 16);
                asm volatile("ldmatrix.sync.aligned.m8n8.x4.shared.b16 {%0,%1,%2,%3}, [%4];"
                    : "=r"(a[mi][0]), "=r"(a[mi][1]), "=r"(a[mi][2]), "=r"(a[mi][3])
                    : "r"(addr));
            }
            uint32_t b[8][2];
            #pragma unroll
            for (int nj = 0; nj < 4; nj++) {
                int nrow = wn + nj * 16 + (lane & 7) + ((lane >> 4) & 1) * 8;
                int c    = kk * 2 + ((lane >> 3) & 1);
                uint32_t addr = sB + nrow * 128 + ((c ^ (nrow & 7)) * 16);
                uint32_t r0, r1, r2, r3;
                asm volatile("ldmatrix.sync.aligned.m8n8.x4.shared.b16 {%0,%1,%2,%3}, [%4];"
                    : "=r"(r0), "=r"(r1), "=r"(r2), "=r"(r3) : "r"(addr));
                b[nj*2][0] = r0; b[nj*2][1] = r1;
                b[nj*2+1][0] = r2; b[nj*2+1][1] = r3;
            }
            #pragma unroll
            for (int mi = 0; mi < 2; mi++)
                #pragma unroll
                for (int ni = 0; ni < 8; ni++)
                    asm volatile(
                        "mma.sync.aligned.m16n8k16.row.col.f32.bf16.bf16.f32 "
                        "{%0,%1,%2,%3}, {%4,%5,%6,%7}, {%8,%9}, {%0,%1,%2,%3};"
                        : "+f"(acc[mi][ni][0]), "+f"(acc[mi][ni][1]),
                          "+f"(acc[mi][ni][2]), "+f"(acc[mi][ni][3])
                        : "r"(a[mi][0]), "r"(a[mi][1]), "r"(a[mi][2]), "r"(a[mi][3]),
                          "r"(b[ni][0]), "r"(b[ni][1]));
        }
        __syncthreads();
    }

    // Epilogue: direct float2 stores from C fragments
    const int g = lane >> 2;
    const int t = lane & 3;
    #pragma unroll
    for (int mi = 0; mi < 2; mi++) {
        #pragma unroll
        for (int ni = 0; ni < 8; ni++) {
            int mg = bm0 + wm + mi * 16 + g;
            int ng = bn0 + wn + ni * 8 + t * 2;
            size_t base0, base1;
            if (headmode) {
                int b0 = mg >> 11, s0 = mg & (SEQ - 1);
                int h  = ng >> 6,  dk = ng & (HD - 1);
                base0 = ((size_t)(b0 * NH + h) * SEQ + s0) * HD + dk;
                int mg1 = mg + 8;
                int b1 = mg1 >> 11, s1 = mg1 & (SEQ - 1);
                base1 = ((size_t)(b1 * NH + h) * SEQ + s1) * HD + dk;
            } else {
                base0 = (size_t)mg * DMODEL + ng;
                base1 = (size_t)(mg + 8) * DMODEL + ng;
            }
            *reinterpret_cast<float2*>(&C[base0]) = make_float2(acc[mi][ni][0], acc[mi][ni][1]);
            *reinterpret_cast<float2*>(&C[base1]) = make_float2(acc[mi][ni][2], acc[mi][ni][3]);
        }
    }
}

// ---------------------------------------------------------------------------
// Flash attention forward, fp32, causal (unchanged from R1)
// ---------------------------------------------------------------------------
#define PITCH 68
#define FLASH_SMEM (4 * 64 * PITCH * 4)

__global__ void __launch_bounds__(256)
flash_fwd(const float* __restrict__ Q, const float* __restrict__ K,
          const float* __restrict__ V, float* __restrict__ O)
{
    extern __shared__ float sm[];
    float* sQT = sm;
    float* sKT = sm + 64 * PITCH;
    float* sV  = sm + 2 * 64 * PITCH;
    float* sP  = sm + 3 * 64 * PITCH;

    const int qt  = gridDim.x - 1 - blockIdx.x;
    const int bh  = blockIdx.y;
    const int tid = threadIdx.x;
    const int tx  = tid & 15;
    const int ty  = tid >> 4;

    const float* Qh = Q + (size_t)bh * SEQ * HD;
    const float* Kh = K + (size_t)bh * SEQ * HD;
    const float* Vh = V + (size_t)bh * SEQ * HD;

    #pragma unroll
    for (int l = 0; l < 4; l++) {
        int fi = l * 256 + tid;
        int r  = fi >> 4;
        int v4 = (fi & 15) * 4;
        float4 x = *reinterpret_cast<const float4*>(&Qh[(size_t)(qt * 64 + r) * HD + v4]);
        sQT[(v4 + 0) * PITCH + r] = x.x * 0.125f;
        sQT[(v4 + 1) * PITCH + r] = x.y * 0.125f;
        sQT[(v4 + 2) * PITCH + r] = x.z * 0.125f;
        sQT[(v4 + 3) * PITCH + r] = x.w * 0.125f;
    }

    float o[4][4] = {};
    float mrow[4] = {-1e30f, -1e30f, -1e30f, -1e30f};
    float lrow[4] = {};

    for (int kt = 0; kt <= qt; kt++) {
        __syncthreads();
        #pragma unroll
        for (int l = 0; l < 4; l++) {
            int fi = l * 256 + tid;
            int r  = fi >> 4;
            int v4 = (fi & 15) * 4;
            float4 kx = *reinterpret_cast<const float4*>(&Kh[(size_t)(kt * 64 + r) * HD + v4]);
            sKT[(v4 + 0) * PITCH + r] = kx.x;
            sKT[(v4 + 1) * PITCH + r] = kx.y;
            sKT[(v4 + 2) * PITCH + r] = kx.z;
            sKT[(v4 + 3) * PITCH + r] = kx.w;
            float4 vx = *reinterpret_cast<const float4*>(&Vh[(size_t)(kt * 64 + r) * HD + v4]);
            *reinterpret_cast<float4*>(&sV[r * PITCH + v4]) = vx;
        }
        __syncthreads();

        float s[4][4] = {};
        #pragma unroll 8
        for (int d = 0; d < 64; d++) {
            float4 aq = *reinterpret_cast<float4*>(&sQT[d * PITCH + ty * 4]);
            float4 bk = *reinterpret_cast<float4*>(&sKT[d * PITCH + tx * 4]);
            float a[4] = {aq.x, aq.y, aq.z, aq.w};
            float b[4] = {bk.x, bk.y, bk.z, bk.w};
            #pragma unroll
            for (int i = 0; i < 4; i++)
                #pragma unroll
                for (int j = 0; j < 4; j++)
                    s[i][j] = fmaf(a[i], b[j], s[i][j]);
        }

        if (kt == qt) {
            #pragma unroll
            for (int i = 0; i < 4; i++)
                #pragma unroll
                for (int j = 0; j < 4; j++)
                    if (tx * 4 + j > ty * 4 + i) s[i][j] = -1e30f;
        }

        #pragma unroll
        for (int i = 0; i < 4; i++) {
            float mx = fmaxf(fmaxf(s[i][0], s[i][1]), fmaxf(s[i][2], s[i][3]));
            #pragma unroll
            for (int off = 8; off; off >>= 1)
                mx = fmaxf(mx, __shfl_xor_sync(0xffffffffu, mx, off));
            float mnew = fmaxf(mrow[i], mx);
            float corr = __expf(mrow[i] - mnew);
            float rs = 0.f;
            #pragma unroll
            for (int j = 0; j < 4; j++) {
                float pfx = __expf(s[i][j] - mnew);
                s[i][j] = pfx;
                rs += pfx;
            }
            #pragma unroll
            for (int off = 8; off; off >>= 1)
                rs += __shfl_xor_sync(0xffffffffu, rs, off);
            lrow[i] = lrow[i] * corr + rs;
            mrow[i] = mnew;
            #pragma unroll
            for (int j = 0; j < 4; j++) o[i][j] *= corr;
            *reinterpret_cast<float4*>(&sP[(ty * 4 + i) * PITCH + tx * 4]) =
                make_float4(s[i][0], s[i][1], s[i][2], s[i][3]);
        }
        __syncthreads();

        #pragma unroll 8
        for (int d = 0; d < 64; d++) {
            float4 bv = *reinterpret_cast<float4*>(&sV[d * PITCH + tx * 4]);
            #pragma unroll
            for (int i = 0; i < 4; i++) {
                float a = sP[(ty * 4 + i) * PITCH + d];
                o[i][0] = fmaf(a, bv.x, o[i][0]);
                o[i][1] = fmaf(a, bv.y, o[i][1]);
                o[i][2] = fmaf(a, bv.z, o[i][2]);
                o[i][3] = fmaf(a, bv.w, o[i][3]);
            }
        }
    }

    const int b = bh >> 4;
    const int h = bh & 15;
    #pragma unroll
    for (int i = 0; i < 4; i++) {
        float inv  = 1.0f / lrow[i];
        int   qrow = qt * 64 + ty * 4 + i;
        size_t base = ((size_t)(b * SEQ + qrow)) * DMODEL + h * HD + tx * 4;
        *reinterpret_cast<float4*>(&O[base]) =
            make_float4(o[i][0] * inv, o[i][1] * inv, o[i][2] * inv, o[i][3] * inv);
    }
}

// ---------------------------------------------------------------------------
extern "C" void kernel_launch(void* const* d_in, const int* in_sizes, int n_in,
                              void* d_out, int out_size)
{
    const float* x  = (const float*)d_in[0];
    const float* wq = (const float*)d_in[1];
    const float* wk = (const float*)d_in[2];
    const float* wv = (const float*)d_in[3];
    const float* wo = (const float*)d_in[4];
    float* out = (float*)d_out;

    float *q, *k, *v, *attn;
    __nv_bfloat16 *xh, *xl, *wh, *wl;
    cudaGetSymbolAddress((void**)&q,    g_q);
    cudaGetSymbolAddress((void**)&k,    g_k);
    cudaGetSymbolAddress((void**)&v,    g_v);
    cudaGetSymbolAddress((void**)&attn, g_attn);
    cudaGetSymbolAddress((void**)&xh,   g_xh);
    cudaGetSymbolAddress((void**)&xl,   g_xl);
    cudaGetSymbolAddress((void**)&wh,   g_wh);
    cudaGetSymbolAddress((void**)&wl,   g_wl);

    cudaFuncSetAttribute(gemm_hmma_x3, cudaFuncAttributeMaxDynamicSharedMemorySize, GEMM_SMEM);
    cudaFuncSetAttribute(flash_fwd,    cudaFuncAttributeMaxDynamicSharedMemorySize, FLASH_SMEM);

    const int nx4 = NTOK * DMODEL / 4;
    const int nw4 = DMODEL * DMODEL / 4;
    dim3 gg(DMODEL / 128, NTOK / 128);   // (8, 64)

    split_bf16<<<nx4 / 256, 256>>>(x, xh, xl, nx4);

    split_bf16<<<nw4 / 256, 256>>>(wq, wh, wl, nw4);
    gemm_hmma_x3<<<gg, 256, GEMM_SMEM>>>(xh, xl, wh, wl, q, 1);
    split_bf16<<<nw4 / 256, 256>>>(wk, wh, wl, nw4);
    gemm_hmma_x3<<<gg, 256, GEMM_SMEM>>>(xh, xl, wh, wl, k, 1);
    split_bf16<<<nw4 / 256, 256>>>(wv, wh, wl, nw4);
    gemm_hmma_x3<<<gg, 256, GEMM_SMEM>>>(xh, xl, wh, wl, v, 1);

    flash_fwd<<<dim3(SEQ / 64, BATCH * NH), 256, FLASH_SMEM>>>(q, k, v, attn);

    split_bf16<<<nx4 / 256, 256>>>(attn, xh, xl, nx4);
    split_bf16<<<nw4 / 256, 256>>>(wo, wh, wl, nw4);
    gemm_hmma_x3<<<gg, 256, GEMM_SMEM>>>(xh, xl, wh, wl, out, 0);
}

// round 4
// speedup vs baseline: 3.1291x; 1.9092x over previous
#include <cuda_runtime.h>
#include <cuda_bf16.h>
#include <cstdint>
#include <math.h>

#define BATCH  4
#define SEQ    2048
#define DMODEL 1024
#define NH     16
#define HD     64
#define NTOK   (BATCH*SEQ)

// ---------------- scratch (static device globals) ----------------
__device__ __align__(16) __nv_bfloat16 g_qh[(size_t)BATCH*NH*SEQ*HD];
__device__ __align__(16) __nv_bfloat16 g_ql[(size_t)BATCH*NH*SEQ*HD];
__device__ __align__(16) __nv_bfloat16 g_kh[(size_t)BATCH*NH*SEQ*HD];
__device__ __align__(16) __nv_bfloat16 g_kl[(size_t)BATCH*NH*SEQ*HD];
__device__ __align__(16) __nv_bfloat16 g_vh[(size_t)BATCH*NH*SEQ*HD];
__device__ __align__(16) __nv_bfloat16 g_vl[(size_t)BATCH*NH*SEQ*HD];
__device__ __align__(16) __nv_bfloat16 g_xh[(size_t)NTOK*DMODEL];
__device__ __align__(16) __nv_bfloat16 g_xl[(size_t)NTOK*DMODEL];
__device__ __align__(16) __nv_bfloat16 g_wh[(size_t)DMODEL*DMODEL];
__device__ __align__(16) __nv_bfloat16 g_wl[(size_t)DMODEL*DMODEL];

__device__ __forceinline__ uint32_t smem_u32(const void* p) {
    uint32_t a;
    asm("{ .reg .u64 t; cvta.to.shared.u64 t, %1; cvt.u32.u64 %0, t; }" : "=r"(a) : "l"(p));
    return a;
}
__device__ __forceinline__ void ldsm4(uint32_t* r, uint32_t addr) {
    asm volatile("ldmatrix.sync.aligned.m8n8.x4.shared.b16 {%0,%1,%2,%3}, [%4];"
        : "=r"(r[0]), "=r"(r[1]), "=r"(r[2]), "=r"(r[3]) : "r"(addr));
}
__device__ __forceinline__ void ldsm4t(uint32_t* r, uint32_t addr) {
    asm volatile("ldmatrix.sync.aligned.m8n8.x4.trans.shared.b16 {%0,%1,%2,%3}, [%4];"
        : "=r"(r[0]), "=r"(r[1]), "=r"(r[2]), "=r"(r[3]) : "r"(addr));
}
__device__ __forceinline__ void mma16816(float* c, const uint32_t* a, uint32_t b0, uint32_t b1) {
    asm volatile("mma.sync.aligned.m16n8k16.row.col.f32.bf16.bf16.f32 "
        "{%0,%1,%2,%3}, {%4,%5,%6,%7}, {%8,%9}, {%0,%1,%2,%3};"
        : "+f"(c[0]), "+f"(c[1]), "+f"(c[2]), "+f"(c[3])
        : "r"(a[0]), "r"(a[1]), "r"(a[2]), "r"(a[3]), "r"(b0), "r"(b1));
}
// pack (even->low, odd->high) into bf16 hi/lo split registers
__device__ __forceinline__ void split_pack(float p0, float p1, uint32_t& hi, uint32_t& lo) {
    __nv_bfloat16 h0 = __float2bfloat16(p0), h1 = __float2bfloat16(p1);
    __nv_bfloat16 l0 = __float2bfloat16(p0 - __bfloat162float(h0));
    __nv_bfloat16 l1 = __float2bfloat16(p1 - __bfloat162float(h1));
    __nv_bfloat162 H = __halves2bfloat162(h0, h1);
    __nv_bfloat162 L = __halves2bfloat162(l0, l1);
    hi = *reinterpret_cast<uint32_t*>(&H);
    lo = *reinterpret_cast<uint32_t*>(&L);
}

// ---------------------------------------------------------------------------
// fp32 -> bf16 hi/lo split
// ---------------------------------------------------------------------------
__global__ void __launch_bounds__(256)
split_bf16(const float* __restrict__ src, __nv_bfloat16* __restrict__ hi,
           __nv_bfloat16* __restrict__ lo, int n4)
{
    int i = blockIdx.x * 256 + threadIdx.x;
    if (i >= n4) return;
    float4 x = reinterpret_cast<const float4*>(src)[i];
    uint32_t h0, l0, h1, l1;
    split_pack(x.x, x.y, h0, l0);
    split_pack(x.z, x.w, h1, l1);
    reinterpret_cast<uint32_t*>(hi)[2*i]   = h0;
    reinterpret_cast<uint32_t*>(hi)[2*i+1] = h1;
    reinterpret_cast<uint32_t*>(lo)[2*i]   = l0;
    reinterpret_cast<uint32_t*>(lo)[2*i+1] = l1;
}

// ---------------------------------------------------------------------------
// HMMA GEMM: C = Ah@Bh^T + Ah@Bl^T + Al@Bh^T  (M=8192, N=K=1024)
// headmode=1: write bf16 hi/lo pairs head-scattered [b,h,s,dk] with scale
// headmode=0: write f32 row-major
// ---------------------------------------------------------------------------
#define STAGE_BYTES 32768
#define GEMM_SMEM   (2*STAGE_BYTES)

__device__ __forceinline__ void gemm_issue(
    const __nv_bfloat16* __restrict__ As, const __nv_bfloat16* __restrict__ Bs,
    uint32_t sA, uint32_t sB, int bm0, int bn0, int k0, int tid)
{
    #pragma unroll
    for (int j = 0; j < 4; j++) {
        int id = tid + j * 256;
        int r  = id >> 3;
        int c  = id & 7;
        uint32_t dsw = (uint32_t)(r * 128 + ((c ^ (r & 7)) * 16));
        const void* ga = As + (size_t)(bm0 + r) * DMODEL + k0 + c * 8;
        asm volatile("cp.async.cg.shared.global [%0], [%1], 16;" :: "r"(sA + dsw), "l"(ga));
        const void* gb = Bs + (size_t)(bn0 + r) * DMODEL + k0 + c * 8;
        asm volatile("cp.async.cg.shared.global [%0], [%1], 16;" :: "r"(sB + dsw), "l"(gb));
    }
    asm volatile("cp.async.commit_group;" ::: "memory");
}

__global__ void __launch_bounds__(256)
gemm_hmma_x3(const __nv_bfloat16* __restrict__ Ah, const __nv_bfloat16* __restrict__ Al,
             const __nv_bfloat16* __restrict__ Bh, const __nv_bfloat16* __restrict__ Bl,
             float* __restrict__ Cf, __nv_bfloat16* __restrict__ Ch,
             __nv_bfloat16* __restrict__ Cl, int headmode, float scale)
{
    extern __shared__ char smem[];
    const uint32_t sb = smem_u32(smem);
    const int tid  = threadIdx.x;
    const int wid  = tid >> 5;
    const int lane = tid & 31;
    const int wm   = (wid & 3) * 32;
    const int wn   = (wid >> 2) * 64;
    const int bm0  = blockIdx.y * 128;
    const int bn0  = blockIdx.x * 128;

    float acc[2][8][4] = {};

    gemm_issue(Ah, Bh, sb, sb + 16384, bm0, bn0, 0, tid);

    #pragma unroll 1
    for (int it = 0; it < 48; it++) {
        const int cur = it & 1;
        if (it + 1 < 48) {
            int itn = it + 1;
            int p   = itn >> 4;
            int k0  = (itn & 15) * 64;
            const __nv_bfloat16* As = (p < 2) ? Ah : Al;
            const __nv_bfloat16* Bs = (p == 1) ? Bl : Bh;
            uint32_t sA = sb + (1 - cur) * STAGE_BYTES;
            gemm_issue(As, Bs, sA, sA + 16384, bm0, bn0, k0, tid);
            asm volatile("cp.async.wait_group 1;" ::: "memory");
        } else {
            asm volatile("cp.async.wait_group 0;" ::: "memory");
        }
        __syncthreads();

        const uint32_t sA = sb + cur * STAGE_BYTES;
        const uint32_t sB = sA + 16384;

        #pragma unroll
        for (int kk = 0; kk < 4; kk++) {
            uint32_t a[2][4];
            #pragma unroll
            for (int mi = 0; mi < 2; mi++) {
                int row = wm + mi * 16 + (lane & 15);
                int c   = kk * 2 + (lane >> 4);
                ldsm4(a[mi], sA + row * 128 + ((c ^ (row & 7)) * 16));
            }
            uint32_t b[8][2];
            #pragma unroll
            for (int nj = 0; nj < 4; nj++) {
                int nrow = wn + nj * 16 + (lane & 7) + ((lane >> 4) & 1) * 8;
                int c    = kk * 2 + ((lane >> 3) & 1);
                uint32_t r4[4];
                ldsm4(r4, sB + nrow * 128 + ((c ^ (nrow & 7)) * 16));
                b[nj*2][0] = r4[0]; b[nj*2][1] = r4[1];
                b[nj*2+1][0] = r4[2]; b[nj*2+1][1] = r4[3];
            }
            #pragma unroll
            for (int mi = 0; mi < 2; mi++)
                #pragma unroll
                for (int ni = 0; ni < 8; ni++)
                    mma16816(acc[mi][ni], a[mi], b[ni][0], b[ni][1]);
        }
        __syncthreads();
    }

    const int g = lane >> 2;
    const int t = lane & 3;
    #pragma unroll
    for (int mi = 0; mi < 2; mi++) {
        #pragma unroll
        for (int ni = 0; ni < 8; ni++) {
            int mg = bm0 + wm + mi * 16 + g;
            int ng = bn0 + wn + ni * 8 + t * 2;
            if (headmode) {
                int h  = ng >> 6, dk = ng & (HD - 1);
                int b0 = mg >> 11, s0 = mg & (SEQ - 1);
                size_t base0 = ((size_t)(b0 * NH + h) * SEQ + s0) * HD + dk;
                int mg1 = mg + 8;
                int b1 = mg1 >> 11, s1 = mg1 & (SEQ - 1);
                size_t base1 = ((size_t)(b1 * NH + h) * SEQ + s1) * HD + dk;
                uint32_t hi, lo;
                split_pack(acc[mi][ni][0] * scale, acc[mi][ni][1] * scale, hi, lo);
                *reinterpret_cast<uint32_t*>(&Ch[base0]) = hi;
                *reinterpret_cast<uint32_t*>(&Cl[base0]) = lo;
                split_pack(acc[mi][ni][2] * scale, acc[mi][ni][3] * scale, hi, lo);
                *reinterpret_cast<uint32_t*>(&Ch[base1]) = hi;
                *reinterpret_cast<uint32_t*>(&Cl[base1]) = lo;
            } else {
                size_t base0 = (size_t)mg * DMODEL + ng;
                size_t base1 = (size_t)(mg + 8) * DMODEL + ng;
                *reinterpret_cast<float2*>(&Cf[base0]) = make_float2(acc[mi][ni][0], acc[mi][ni][1]);
                *reinterpret_cast<float2*>(&Cf[base1]) = make_float2(acc[mi][ni][2], acc[mi][ni][3]);
            }
        }
    }
}

// ---------------------------------------------------------------------------
// Flash attention, HMMA bf16 3-term split, causal.
// Br=128 (8 warps x 16 rows), Bc=64. Q pre-scaled by 0.125 upstream.
// Output written as bf16 hi/lo into the final-GEMM input buffers.
// ---------------------------------------------------------------------------
#define SQH 0
#define SQL 16384
#define SKV0 32768
#define KVSTG 32768
#define FLASH_SMEM (SKV0 + 2*KVSTG)   // 98304

__device__ __forceinline__ void flash_issue_kv(
    const __nv_bfloat16* Kh, const __nv_bfloat16* Kl,
    const __nv_bfloat16* Vh, const __nv_bfloat16* Vl,
    uint32_t kvb, size_t gbase, int tid)
{
    const __nv_bfloat16* srcs[4] = {Kh, Kl, Vh, Vl};
    #pragma unroll
    for (int j = 0; j < 8; j++) {
        int idx = (j & 1) * 256 + tid;          // 0..511
        int row = idx >> 3;
        int c   = idx & 7;
        uint32_t dst = kvb + (uint32_t)(j >> 1) * 8192 + row * 128 + ((c ^ (row & 7)) * 16);
        const void* src = srcs[j >> 1] + gbase + (size_t)row * HD + c * 8;
        asm volatile("cp.async.cg.shared.global [%0], [%1], 16;" :: "r"(dst), "l"(src));
    }
    asm volatile("cp.async.commit_group;" ::: "memory");
}

__global__ void __launch_bounds__(256, 2)
flash_hmma(const __nv_bfloat16* __restrict__ Qh, const __nv_bfloat16* __restrict__ Ql,
           const __nv_bfloat16* __restrict__ Kh, const __nv_bfloat16* __restrict__ Kl,
           const __nv_bfloat16* __restrict__ Vh, const __nv_bfloat16* __restrict__ Vl,
           __nv_bfloat16* __restrict__ Oh, __nv_bfloat16* __restrict__ Ol)
{
    extern __shared__ char smem[];
    const uint32_t sb = smem_u32(smem);
    const int tid  = threadIdx.x;
    const int wid  = tid >> 5;
    const int lane = tid & 31;
    const int qt   = gridDim.x - 1 - blockIdx.x;   // long CTAs first
    const int bh   = blockIdx.y;
    const int nkt  = 2 * qt + 2;

    // Q tile loads (128 rows x 64 dk, hi+lo)
    {
        size_t qbase = ((size_t)bh * SEQ + qt * 128) * HD;
        #pragma unroll
        for (int j = 0; j < 8; j++) {
            int idx = (j & 3) * 256 + tid;       // 0..1023
            int row = idx >> 3;
            int c   = idx & 7;
            uint32_t dst = sb + (j < 4 ? SQH : SQL) + row * 128 + ((c ^ (row & 7)) * 16);
            const void* src = (j < 4 ? Qh : Ql) + qbase + (size_t)row * HD + c * 8;
            asm volatile("cp.async.cg.shared.global [%0], [%1], 16;" :: "r"(dst), "l"(src));
        }
    }
    flash_issue_kv(Kh, Kl, Vh, Vl, sb + SKV0, (size_t)bh * SEQ * HD, tid);

    float o[8][4] = {};
    float m0 = -1e30f, m1 = -1e30f, l0 = 0.f, l1 = 0.f;

    for (int kt = 0; kt < nkt; kt++) {
        if (kt + 1 < nkt) {
            flash_issue_kv(Kh, Kl, Vh, Vl,
                           sb + SKV0 + ((kt + 1) & 1) * KVSTG,
                           ((size_t)bh * SEQ + (kt + 1) * 64) * HD, tid);
            asm volatile("cp.async.wait_group 1;" ::: "memory");
        } else {
            asm volatile("cp.async.wait_group 0;" ::: "memory");
        }
        __syncthreads();

        const uint32_t kvb = sb + SKV0 + (kt & 1) * KVSTG;

        // ---- S = Qh@Kh + Ql@Kh + Qh@Kl ----
        float s[8][4] = {};
        #pragma unroll
        for (int kc = 0; kc < 4; kc++) {
            uint32_t qh4[4], ql4[4];
            {
                int row = wid * 16 + (lane & 15);
                int c   = kc * 2 + (lane >> 4);
                uint32_t off = row * 128 + ((c ^ (row & 7)) * 16);
                ldsm4(qh4, sb + SQH + off);
                ldsm4(ql4, sb + SQL + off);
            }
            #pragma unroll
            for (int nj = 0; nj < 4; nj++) {
                int nrow = nj * 16 + (lane & 7) + ((lane >> 4) & 1) * 8;
                int c    = kc * 2 + ((lane >> 3) & 1);
                uint32_t off = nrow * 128 + ((c ^ (nrow & 7)) * 16);
                uint32_t kh4[4], kl4[4];
                ldsm4(kh4, kvb + off);
                ldsm4(kl4, kvb + 8192 + off);
                mma16816(s[2*nj],   qh4, kh4[0], kh4[1]);
                mma16816(s[2*nj],   ql4, kh4[0], kh4[1]);
                mma16816(s[2*nj],   qh4, kl4[0], kl4[1]);
                mma16816(s[2*nj+1], qh4, kh4[2], kh4[3]);
                mma16816(s[2*nj+1], ql4, kh4[2], kh4[3]);
                mma16816(s[2*nj+1], qh4, kl4[2], kl4[3]);
            }
        }

        // ---- causal mask (diagonal tiles only) ----
        if (kt >= 2 * qt) {
            int rbase = qt * 128 + wid * 16 + (lane >> 2);
            #pragma unroll
            for (int ni = 0; ni < 8; ni++) {
                int colb = kt * 64 + ni * 8 + (lane & 3) * 2;
                if (colb     > rbase)     s[ni][0] = -1e30f;
                if (colb + 1 > rbase)     s[ni][1] = -1e30f;
                if (colb     > rbase + 8) s[ni][2] = -1e30f;
                if (colb + 1 > rbase + 8) s[ni][3] = -1e30f;
            }
        }

        // ---- online softmax ----
        float rx0 = -1e30f, rx1 = -1e30f;
        #pragma unroll
        for (int ni = 0; ni < 8; ni++) {
            rx0 = fmaxf(rx0, fmaxf(s[ni][0], s[ni][1]));
            rx1 = fmaxf(rx1, fmaxf(s[ni][2], s[ni][3]));
        }
        rx0 = fmaxf(rx0, __shfl_xor_sync(0xffffffffu, rx0, 1));
        rx0 = fmaxf(rx0, __shfl_xor_sync(0xffffffffu, rx0, 2));
        rx1 = fmaxf(rx1, __shfl_xor_sync(0xffffffffu, rx1, 1));
        rx1 = fmaxf(rx1, __shfl_xor_sync(0xffffffffu, rx1, 2));
        float mn0 = fmaxf(m0, rx0), mn1 = fmaxf(m1, rx1);
        float cor0 = __expf(m0 - mn0), cor1 = __expf(m1 - mn1);
        m0 = mn0; m1 = mn1;
        float sum0 = 0.f, sum1 = 0.f;
        #pragma unroll
        for (int ni = 0; ni < 8; ni++) {
            s[ni][0] = __expf(s[ni][0] - mn0); sum0 += s[ni][0];
            s[ni][1] = __expf(s[ni][1] - mn0); sum0 += s[ni][1];
            s[ni][2] = __expf(s[ni][2] - mn1); sum1 += s[ni][2];
            s[ni][3] = __expf(s[ni][3] - mn1); sum1 += s[ni][3];
        }
        sum0 += __shfl_xor_sync(0xffffffffu, sum0, 1);
        sum0 += __shfl_xor_sync(0xffffffffu, sum0, 2);
        sum1 += __shfl_xor_sync(0xffffffffu, sum1, 1);
        sum1 += __shfl_xor_sync(0xffffffffu, sum1, 2);
        l0 = l0 * cor0 + sum0;
        l1 = l1 * cor1 + sum1;
        #pragma unroll
        for (int ni = 0; ni < 8; ni++) {
            o[ni][0] *= cor0; o[ni][1] *= cor0;
            o[ni][2] *= cor1; o[ni][3] *= cor1;
        }

        // ---- O += Ph@Vh + Pl@Vh + Ph@Vl ----
        #pragma unroll
        for (int kc = 0; kc < 4; kc++) {
            uint32_t ah[4], al[4];
            split_pack(s[2*kc][0],   s[2*kc][1],   ah[0], al[0]);
            split_pack(s[2*kc][2],   s[2*kc][3],   ah[1], al[1]);
            split_pack(s[2*kc+1][0], s[2*kc+1][1], ah[2], al[2]);
            split_pack(s[2*kc+1][2], s[2*kc+1][3], ah[3], al[3]);
            #pragma unroll
            for (int nj = 0; nj < 4; nj++) {
                int row = kc * 16 + ((lane >> 3) & 1) * 8 + (lane & 7);
                int c   = 2 * nj + (lane >> 4);
                uint32_t off = row * 128 + ((c ^ (row & 7)) * 16);
                uint32_t vh4[4], vl4[4];
                ldsm4t(vh4, kvb + 16384 + off);
                ldsm4t(vl4, kvb + 24576 + off);
                mma16816(o[2*nj],   ah, vh4[0], vh4[1]);
                mma16816(o[2*nj],   al, vh4[0], vh4[1]);
                mma16816(o[2*nj],   ah, vl4[0], vl4[1]);
                mma16816(o[2*nj+1], ah, vh4[2], vh4[3]);
                mma16816(o[2*nj+1], al, vh4[2], vh4[3]);
                mma16816(o[2*nj+1], ah, vl4[2], vl4[3]);
            }
        }
        __syncthreads();
    }

    // ---- epilogue: normalize, split, write [b, s, h*64+dk] hi/lo ----
    const float inv0 = 1.f / l0, inv1 = 1.f / l1;
    const int b = bh >> 4, h = bh & 15;
    const int r = lane >> 2, t = lane & 3;
    const int sg0 = qt * 128 + wid * 16 + r;
    #pragma unroll
    for (int ni = 0; ni < 8; ni++) {
        int col = h * 64 + ni * 8 + t * 2;
        uint32_t hi, lo;
        size_t i0 = (size_t)(b * SEQ + sg0) * DMODEL + col;
        split_pack(o[ni][0] * inv0, o[ni][1] * inv0, hi, lo);
        *reinterpret_cast<uint32_t*>(&Oh[i0]) = hi;
        *reinterpret_cast<uint32_t*>(&Ol[i0]) = lo;
        size_t i1 = (size_t)(b * SEQ + sg0 + 8) * DMODEL + col;
        split_pack(o[ni][2] * inv1, o[ni][3] * inv1, hi, lo);
        *reinterpret_cast<uint32_t*>(&Oh[i1]) = hi;
        *reinterpret_cast<uint32_t*>(&Ol[i1]) = lo;
    }
}

// ---------------------------------------------------------------------------
extern "C" void kernel_launch(void* const* d_in, const int* in_sizes, int n_in,
                              void* d_out, int out_size)
{
    const float* x  = (const float*)d_in[0];
    const float* wq = (const float*)d_in[1];
    const float* wk = (const float*)d_in[2];
    const float* wv = (const float*)d_in[3];
    const float* wo = (const float*)d_in[4];
    float* out = (float*)d_out;

    __nv_bfloat16 *qh, *ql, *kh, *kl, *vh, *vl, *xh, *xl, *wh, *wl;
    cudaGetSymbolAddress((void**)&qh, g_qh);
    cudaGetSymbolAddress((void**)&ql, g_ql);
    cudaGetSymbolAddress((void**)&kh, g_kh);
    cudaGetSymbolAddress((void**)&kl, g_kl);
    cudaGetSymbolAddress((void**)&vh, g_vh);
    cudaGetSymbolAddress((void**)&vl, g_vl);
    cudaGetSymbolAddress((void**)&xh, g_xh);
    cudaGetSymbolAddress((void**)&xl, g_xl);
    cudaGetSymbolAddress((void**)&wh, g_wh);
    cudaGetSymbolAddress((void**)&wl, g_wl);

    cudaFuncSetAttribute(gemm_hmma_x3, cudaFuncAttributeMaxDynamicSharedMemorySize, GEMM_SMEM);
    cudaFuncSetAttribute(flash_hmma,   cudaFuncAttributeMaxDynamicSharedMemorySize, FLASH_SMEM);

    const int nx4 = NTOK * DMODEL / 4;
    const int nw4 = DMODEL * DMODEL / 4;
    dim3 gg(DMODEL / 128, NTOK / 128);

    split_bf16<<<nx4 / 256, 256>>>(x, xh, xl, nx4);

    split_bf16<<<nw4 / 256, 256>>>(wq, wh, wl, nw4);
    gemm_hmma_x3<<<gg, 256, GEMM_SMEM>>>(xh, xl, wh, wl, nullptr, qh, ql, 1, 0.125f);
    split_bf16<<<nw4 / 256, 256>>>(wk, wh, wl, nw4);
    gemm_hmma_x3<<<gg, 256, GEMM_SMEM>>>(xh, xl, wh, wl, nullptr, kh, kl, 1, 1.0f);
    split_bf16<<<nw4 / 256, 256>>>(wv, wh, wl, nw4);
    gemm_hmma_x3<<<gg, 256, GEMM_SMEM>>>(xh, xl, wh, wl, nullptr, vh, vl, 1, 1.0f);

    flash_hmma<<<dim3(SEQ / 128, BATCH * NH), 256, FLASH_SMEM>>>(qh, ql, kh, kl, vh, vl, xh, xl);

    split_bf16<<<nw4 / 256, 256>>>(wo, wh, wl, nw4);
    gemm_hmma_x3<<<gg, 256, GEMM_SMEM>>>(xh, xl, wh, wl, out, nullptr, nullptr, 0, 1.0f);
}

// round 5
// speedup vs baseline: 3.2242x; 1.0304x over previous
#include <cuda_runtime.h>
#include <cuda_bf16.h>
#include <cstdint>
#include <math.h>

#define BATCH  4
#define SEQ    2048
#define DMODEL 1024
#define NH     16
#define HD     64
#define NTOK   (BATCH*SEQ)

// ---------------- scratch (static device globals) ----------------
__device__ __align__(16) __nv_bfloat16 g_qh[(size_t)BATCH*NH*SEQ*HD];
__device__ __align__(16) __nv_bfloat16 g_ql[(size_t)BATCH*NH*SEQ*HD];
__device__ __align__(16) __nv_bfloat16 g_kh[(size_t)BATCH*NH*SEQ*HD];
__device__ __align__(16) __nv_bfloat16 g_kl[(size_t)BATCH*NH*SEQ*HD];
__device__ __align__(16) __nv_bfloat16 g_vh[(size_t)BATCH*NH*SEQ*HD];
__device__ __align__(16) __nv_bfloat16 g_vl[(size_t)BATCH*NH*SEQ*HD];
__device__ __align__(16) __nv_bfloat16 g_xh[(size_t)NTOK*DMODEL];
__device__ __align__(16) __nv_bfloat16 g_xl[(size_t)NTOK*DMODEL];
__device__ __align__(16) __nv_bfloat16 g_w0h[(size_t)DMODEL*DMODEL];
__device__ __align__(16) __nv_bfloat16 g_w0l[(size_t)DMODEL*DMODEL];
__device__ __align__(16) __nv_bfloat16 g_w1h[(size_t)DMODEL*DMODEL];
__device__ __align__(16) __nv_bfloat16 g_w1l[(size_t)DMODEL*DMODEL];
__device__ __align__(16) __nv_bfloat16 g_w2h[(size_t)DMODEL*DMODEL];
__device__ __align__(16) __nv_bfloat16 g_w2l[(size_t)DMODEL*DMODEL];

__device__ __forceinline__ uint32_t smem_u32(const void* p) {
    uint32_t a;
    asm("{ .reg .u64 t; cvta.to.shared.u64 t, %1; cvt.u32.u64 %0, t; }" : "=r"(a) : "l"(p));
    return a;
}
__device__ __forceinline__ void ldsm4(uint32_t* r, uint32_t addr) {
    asm volatile("ldmatrix.sync.aligned.m8n8.x4.shared.b16 {%0,%1,%2,%3}, [%4];"
        : "=r"(r[0]), "=r"(r[1]), "=r"(r[2]), "=r"(r[3]) : "r"(addr));
}
__device__ __forceinline__ void ldsm4t(uint32_t* r, uint32_t addr) {
    asm volatile("ldmatrix.sync.aligned.m8n8.x4.trans.shared.b16 {%0,%1,%2,%3}, [%4];"
        : "=r"(r[0]), "=r"(r[1]), "=r"(r[2]), "=r"(r[3]) : "r"(addr));
}
__device__ __forceinline__ void mma16816(float* c, const uint32_t* a, uint32_t b0, uint32_t b1) {
    asm volatile("mma.sync.aligned.m16n8k16.row.col.f32.bf16.bf16.f32 "
        "{%0,%1,%2,%3}, {%4,%5,%6,%7}, {%8,%9}, {%0,%1,%2,%3};"
        : "+f"(c[0]), "+f"(c[1]), "+f"(c[2]), "+f"(c[3])
        : "r"(a[0]), "r"(a[1]), "r"(a[2]), "r"(a[3]), "r"(b0), "r"(b1));
}
__device__ __forceinline__ void split_pack(float p0, float p1, uint32_t& hi, uint32_t& lo) {
    __nv_bfloat16 h0 = __float2bfloat16(p0), h1 = __float2bfloat16(p1);
    __nv_bfloat16 l0 = __float2bfloat16(p0 - __bfloat162float(h0));
    __nv_bfloat16 l1 = __float2bfloat16(p1 - __bfloat162float(h1));
    __nv_bfloat162 H = __halves2bfloat162(h0, h1);
    __nv_bfloat162 L = __halves2bfloat162(l0, l1);
    hi = *reinterpret_cast<uint32_t*>(&H);
    lo = *reinterpret_cast<uint32_t*>(&L);
}

// ---------------------------------------------------------------------------
__global__ void __launch_bounds__(256)
split_bf16(const float* __restrict__ src, __nv_bfloat16* __restrict__ hi,
           __nv_bfloat16* __restrict__ lo, int n4)
{
    int i = blockIdx.x * 256 + threadIdx.x;
    if (i >= n4) return;
    float4 x = reinterpret_cast<const float4*>(src)[i];
    uint32_t h0, l0, h1, l1;
    split_pack(x.x, x.y, h0, l0);
    split_pack(x.z, x.w, h1, l1);
    reinterpret_cast<uint32_t*>(hi)[2*i]   = h0;
    reinterpret_cast<uint32_t*>(hi)[2*i+1] = h1;
    reinterpret_cast<uint32_t*>(lo)[2*i]   = l0;
    reinterpret_cast<uint32_t*>(lo)[2*i+1] = l1;
}

// ---------------------------------------------------------------------------
// Fused 3-term split GEMM. All 4 tiles (Ah,Al,Bh,Bl) resident per K-chunk.
// CTA 128x128, BK=64, 3-stage cp.async pipeline (192KB smem).
// qkv_mode=1: blockIdx.z selects W/output; writes bf16 hi/lo head-scattered.
// qkv_mode=0: single B, f32 row-major output.
// ---------------------------------------------------------------------------
#define TSTAGE 65536
#define GEMM_SMEM (3*TSTAGE)
#define NKIT 16

__device__ __forceinline__ void issue_tile(const __nv_bfloat16* __restrict__ src,
                                           int row0, int k0, uint32_t dst, int tid)
{
    #pragma unroll
    for (int j = 0; j < 4; j++) {
        int id = tid + j * 256;
        int r  = id >> 3;
        int c  = id & 7;
        uint32_t off = (uint32_t)(r * 128 + ((c ^ (r & 7)) * 16));
        const void* g = src + (size_t)(row0 + r) * DMODEL + k0 + c * 8;
        asm volatile("cp.async.cg.shared.global [%0], [%1], 16;" :: "r"(dst + off), "l"(g));
    }
}

__global__ void __launch_bounds__(256, 1)
gemm_x3(const __nv_bfloat16* __restrict__ Ah, const __nv_bfloat16* __restrict__ Al,
        const __nv_bfloat16* __restrict__ B0h, const __nv_bfloat16* __restrict__ B0l,
        const __nv_bfloat16* __restrict__ B1h, const __nv_bfloat16* __restrict__ B1l,
        const __nv_bfloat16* __restrict__ B2h, const __nv_bfloat16* __restrict__ B2l,
        float* __restrict__ Cf,
        __nv_bfloat16* __restrict__ C0h, __nv_bfloat16* __restrict__ C0l,
        __nv_bfloat16* __restrict__ C1h, __nv_bfloat16* __restrict__ C1l,
        __nv_bfloat16* __restrict__ C2h, __nv_bfloat16* __restrict__ C2l,
        int qkv_mode)
{
    extern __shared__ char smem[];
    const uint32_t sb = smem_u32(smem);
    const int tid  = threadIdx.x;
    const int wid  = tid >> 5;
    const int lane = tid & 31;
    const int wm   = (wid & 3) * 32;
    const int wn   = (wid >> 2) * 64;
    const int bm0  = blockIdx.y * 128;
    const int bn0  = blockIdx.x * 128;
    const int z    = blockIdx.z;

    const __nv_bfloat16 *Bh, *Bl;
    __nv_bfloat16 *Ch = nullptr, *Cl = nullptr;
    float scale = 1.0f;
    if (z == 0)      { Bh = B0h; Bl = B0l; Ch = C0h; Cl = C0l; scale = qkv_mode ? 0.125f : 1.0f; }
    else if (z == 1) { Bh = B1h; Bl = B1l; Ch = C1h; Cl = C1l; }
    else             { Bh = B2h; Bl = B2l; Ch = C2h; Cl = C2l; }

    // prologue: stages 0,1
    #pragma unroll
    for (int s = 0; s < 2; s++) {
        uint32_t st = sb + s * TSTAGE;
        issue_tile(Ah, bm0, s * 64, st,         tid);
        issue_tile(Al, bm0, s * 64, st + 16384, tid);
        issue_tile(Bh, bn0, s * 64, st + 32768, tid);
        issue_tile(Bl, bn0, s * 64, st + 49152, tid);
        asm volatile("cp.async.commit_group;" ::: "memory");
    }

    float acc[2][8][4] = {};

    #pragma unroll 1
    for (int it = 0; it < NKIT; it++) {
        if (it + 2 < NKIT) {
            int t = it + 2;
            uint32_t st = sb + (t % 3) * TSTAGE;
            issue_tile(Ah, bm0, t * 64, st,         tid);
            issue_tile(Al, bm0, t * 64, st + 16384, tid);
            issue_tile(Bh, bn0, t * 64, st + 32768, tid);
            issue_tile(Bl, bn0, t * 64, st + 49152, tid);
            asm volatile("cp.async.commit_group;" ::: "memory");
            asm volatile("cp.async.wait_group 2;" ::: "memory");
        } else if (it + 2 == NKIT) {
            asm volatile("cp.async.wait_group 1;" ::: "memory");
        } else {
            asm volatile("cp.async.wait_group 0;" ::: "memory");
        }
        __syncthreads();

        const uint32_t st  = sb + (it % 3) * TSTAGE;
        const uint32_t sAh = st, sAl = st + 16384, sBh = st + 32768, sBl = st + 49152;

        #pragma unroll
        for (int kk = 0; kk < 4; kk++) {
            uint32_t ah[2][4], al[2][4];
            #pragma unroll
            for (int mi = 0; mi < 2; mi++) {
                int row = wm + mi * 16 + (lane & 15);
                int c   = kk * 2 + (lane >> 4);
                uint32_t off = row * 128 + ((c ^ (row & 7)) * 16);
                ldsm4(ah[mi], sAh + off);
                ldsm4(al[mi], sAl + off);
            }
            uint32_t bh[8][2], bl[8][2];
            #pragma unroll
            for (int nj = 0; nj < 4; nj++) {
                int nrow = wn + nj * 16 + (lane & 7) + ((lane >> 4) & 1) * 8;
                int c    = kk * 2 + ((lane >> 3) & 1);
                uint32_t off = nrow * 128 + ((c ^ (nrow & 7)) * 16);
                uint32_t rh[4], rl[4];
                ldsm4(rh, sBh + off);
                ldsm4(rl, sBl + off);
                bh[nj*2][0] = rh[0]; bh[nj*2][1] = rh[1];
                bh[nj*2+1][0] = rh[2]; bh[nj*2+1][1] = rh[3];
                bl[nj*2][0] = rl[0]; bl[nj*2][1] = rl[1];
                bl[nj*2+1][0] = rl[2]; bl[nj*2+1][1] = rl[3];
            }
            #pragma unroll
            for (int mi = 0; mi < 2; mi++)
                #pragma unroll
                for (int ni = 0; ni < 8; ni++) {
                    mma16816(acc[mi][ni], ah[mi], bh[ni][0], bh[ni][1]);
                    mma16816(acc[mi][ni], al[mi], bh[ni][0], bh[ni][1]);
                    mma16816(acc[mi][ni], ah[mi], bl[ni][0], bl[ni][1]);
                }
        }
        __syncthreads();
    }

    // epilogue
    const int g = lane >> 2;
    const int t = lane & 3;
    #pragma unroll
    for (int mi = 0; mi < 2; mi++) {
        #pragma unroll
        for (int ni = 0; ni < 8; ni++) {
            int mg = bm0 + wm + mi * 16 + g;
            int ng = bn0 + wn + ni * 8 + t * 2;
            if (qkv_mode) {
                int h  = ng >> 6, dk = ng & (HD - 1);
                int b0 = mg >> 11, s0 = mg & (SEQ - 1);
                size_t base0 = ((size_t)(b0 * NH + h) * SEQ + s0) * HD + dk;
                int mg1 = mg + 8;
                int b1 = mg1 >> 11, s1 = mg1 & (SEQ - 1);
                size_t base1 = ((size_t)(b1 * NH + h) * SEQ + s1) * HD + dk;
                uint32_t hi, lo;
                split_pack(acc[mi][ni][0] * scale, acc[mi][ni][1] * scale, hi, lo);
                *reinterpret_cast<uint32_t*>(&Ch[base0]) = hi;
                *reinterpret_cast<uint32_t*>(&Cl[base0]) = lo;
                split_pack(acc[mi][ni][2] * scale, acc[mi][ni][3] * scale, hi, lo);
                *reinterpret_cast<uint32_t*>(&Ch[base1]) = hi;
                *reinterpret_cast<uint32_t*>(&Cl[base1]) = lo;
            } else {
                size_t base0 = (size_t)mg * DMODEL + ng;
                size_t base1 = (size_t)(mg + 8) * DMODEL + ng;
                *reinterpret_cast<float2*>(&Cf[base0]) = make_float2(acc[mi][ni][0], acc[mi][ni][1]);
                *reinterpret_cast<float2*>(&Cf[base1]) = make_float2(acc[mi][ni][2], acc[mi][ni][3]);
            }
        }
    }
}

// ---------------------------------------------------------------------------
// Flash attention, HMMA bf16 3-term split, causal. (unchanged from R4)
// ---------------------------------------------------------------------------
#define SQH 0
#define SQL 16384
#define SKV0 32768
#define KVSTG 32768
#define FLASH_SMEM (SKV0 + 2*KVSTG)

__device__ __forceinline__ void flash_issue_kv(
    const __nv_bfloat16* Kh, const __nv_bfloat16* Kl,
    const __nv_bfloat16* Vh, const __nv_bfloat16* Vl,
    uint32_t kvb, size_t gbase, int tid)
{
    const __nv_bfloat16* srcs[4] = {Kh, Kl, Vh, Vl};
    #pragma unroll
    for (int j = 0; j < 8; j++) {
        int idx = (j & 1) * 256 + tid;
        int row = idx >> 3;
        int c   = idx & 7;
        uint32_t dst = kvb + (uint32_t)(j >> 1) * 8192 + row * 128 + ((c ^ (row & 7)) * 16);
        const void* src = srcs[j >> 1] + gbase + (size_t)row * HD + c * 8;
        asm volatile("cp.async.cg.shared.global [%0], [%1], 16;" :: "r"(dst), "l"(src));
    }
    asm volatile("cp.async.commit_group;" ::: "memory");
}

__global__ void __launch_bounds__(256, 2)
flash_hmma(const __nv_bfloat16* __restrict__ Qh, const __nv_bfloat16* __restrict__ Ql,
           const __nv_bfloat16* __restrict__ Kh, const __nv_bfloat16* __restrict__ Kl,
           const __nv_bfloat16* __restrict__ Vh, const __nv_bfloat16* __restrict__ Vl,
           __nv_bfloat16* __restrict__ Oh, __nv_bfloat16* __restrict__ Ol)
{
    extern __shared__ char smem[];
    const uint32_t sb = smem_u32(smem);
    const int tid  = threadIdx.x;
    const int wid  = tid >> 5;
    const int lane = tid & 31;
    const int qt   = gridDim.x - 1 - blockIdx.x;
    const int bh   = blockIdx.y;
    const int nkt  = 2 * qt + 2;

    {
        size_t qbase = ((size_t)bh * SEQ + qt * 128) * HD;
        #pragma unroll
        for (int j = 0; j < 8; j++) {
            int idx = (j & 3) * 256 + tid;
            int row = idx >> 3;
            int c   = idx & 7;
            uint32_t dst = sb + (j < 4 ? SQH : SQL) + row * 128 + ((c ^ (row & 7)) * 16);
            const void* src = (j < 4 ? Qh : Ql) + qbase + (size_t)row * HD + c * 8;
            asm volatile("cp.async.cg.shared.global [%0], [%1], 16;" :: "r"(dst), "l"(src));
        }
    }
    flash_issue_kv(Kh, Kl, Vh, Vl, sb + SKV0, (size_t)bh * SEQ * HD, tid);

    float o[8][4] = {};
    float m0 = -1e30f, m1 = -1e30f, l0 = 0.f, l1 = 0.f;

    for (int kt = 0; kt < nkt; kt++) {
        if (kt + 1 < nkt) {
            flash_issue_kv(Kh, Kl, Vh, Vl,
                           sb + SKV0 + ((kt + 1) & 1) * KVSTG,
                           ((size_t)bh * SEQ + (kt + 1) * 64) * HD, tid);
            asm volatile("cp.async.wait_group 1;" ::: "memory");
        } else {
            asm volatile("cp.async.wait_group 0;" ::: "memory");
        }
        __syncthreads();

        const uint32_t kvb = sb + SKV0 + (kt & 1) * KVSTG;

        float s[8][4] = {};
        #pragma unroll
        for (int kc = 0; kc < 4; kc++) {
            uint32_t qh4[4], ql4[4];
            {
                int row = wid * 16 + (lane & 15);
                int c   = kc * 2 + (lane >> 4);
                uint32_t off = row * 128 + ((c ^ (row & 7)) * 16);
                ldsm4(qh4, sb + SQH + off);
                ldsm4(ql4, sb + SQL + off);
            }
            #pragma unroll
            for (int nj = 0; nj < 4; nj++) {
                int nrow = nj * 16 + (lane & 7) + ((lane >> 4) & 1) * 8;
                int c    = kc * 2 + ((lane >> 3) & 1);
                uint32_t off = nrow * 128 + ((c ^ (nrow & 7)) * 16);
                uint32_t kh4[4], kl4[4];
                ldsm4(kh4, kvb + off);
                ldsm4(kl4, kvb + 8192 + off);
                mma16816(s[2*nj],   qh4, kh4[0], kh4[1]);
                mma16816(s[2*nj],   ql4, kh4[0], kh4[1]);
                mma16816(s[2*nj],   qh4, kl4[0], kl4[1]);
                mma16816(s[2*nj+1], qh4, kh4[2], kh4[3]);
                mma16816(s[2*nj+1], ql4, kh4[2], kh4[3]);
                mma16816(s[2*nj+1], qh4, kl4[2], kl4[3]);
            }
        }

        if (kt >= 2 * qt) {
            int rbase = qt * 128 + wid * 16 + (lane >> 2);
            #pragma unroll
            for (int ni = 0; ni < 8; ni++) {
                int colb = kt * 64 + ni * 8 + (lane & 3) * 2;
                if (colb     > rbase)     s[ni][0] = -1e30f;
                if (colb + 1 > rbase)     s[ni][1] = -1e30f;
                if (colb     > rbase + 8) s[ni][2] = -1e30f;
                if (colb + 1 > rbase + 8) s[ni][3] = -1e30f;
            }
        }

        float rx0 = -1e30f, rx1 = -1e30f;
        #pragma unroll
        for (int ni = 0; ni < 8; ni++) {
            rx0 = fmaxf(rx0, fmaxf(s[ni][0], s[ni][1]));
            rx1 = fmaxf(rx1, fmaxf(s[ni][2], s[ni][3]));
        }
        rx0 = fmaxf(rx0, __shfl_xor_sync(0xffffffffu, rx0, 1));
        rx0 = fmaxf(rx0, __shfl_xor_sync(0xffffffffu, rx0, 2));
        rx1 = fmaxf(rx1, __shfl_xor_sync(0xffffffffu, rx1, 1));
        rx1 = fmaxf(rx1, __shfl_xor_sync(0xffffffffu, rx1, 2));
        float mn0 = fmaxf(m0, rx0), mn1 = fmaxf(m1, rx1);
        float cor0 = __expf(m0 - mn0), cor1 = __expf(m1 - mn1);
        m0 = mn0; m1 = mn1;
        float sum0 = 0.f, sum1 = 0.f;
        #pragma unroll
        for (int ni = 0; ni < 8; ni++) {
            s[ni][0] = __expf(s[ni][0] - mn0); sum0 += s[ni][0];
            s[ni][1] = __expf(s[ni][1] - mn0); sum0 += s[ni][1];
            s[ni][2] = __expf(s[ni][2] - mn1); sum1 += s[ni][2];
            s[ni][3] = __expf(s[ni][3] - mn1); sum1 += s[ni][3];
        }
        sum0 += __shfl_xor_sync(0xffffffffu, sum0, 1);
        sum0 += __shfl_xor_sync(0xffffffffu, sum0, 2);
        sum1 += __shfl_xor_sync(0xffffffffu, sum1, 1);
        sum1 += __shfl_xor_sync(0xffffffffu, sum1, 2);
        l0 = l0 * cor0 + sum0;
        l1 = l1 * cor1 + sum1;
        #pragma unroll
        for (int ni = 0; ni < 8; ni++) {
            o[ni][0] *= cor0; o[ni][1] *= cor0;
            o[ni][2] *= cor1; o[ni][3] *= cor1;
        }

        #pragma unroll
        for (int kc = 0; kc < 4; kc++) {
            uint32_t ah[4], al[4];
            split_pack(s[2*kc][0],   s[2*kc][1],   ah[0], al[0]);
            split_pack(s[2*kc][2],   s[2*kc][3],   ah[1], al[1]);
            split_pack(s[2*kc+1][0], s[2*kc+1][1], ah[2], al[2]);
            split_pack(s[2*kc+1][2], s[2*kc+1][3], ah[3], al[3]);
            #pragma unroll
            for (int nj = 0; nj < 4; nj++) {
                int row = kc * 16 + ((lane >> 3) & 1) * 8 + (lane & 7);
                int c   = 2 * nj + (lane >> 4);
                uint32_t off = row * 128 + ((c ^ (row & 7)) * 16);
                uint32_t vh4[4], vl4[4];
                ldsm4t(vh4, kvb + 16384 + off);
                ldsm4t(vl4, kvb + 24576 + off);
                mma16816(o[2*nj],   ah, vh4[0], vh4[1]);
                mma16816(o[2*nj],   al, vh4[0], vh4[1]);
                mma16816(o[2*nj],   ah, vl4[0], vl4[1]);
                mma16816(o[2*nj+1], ah, vh4[2], vh4[3]);
                mma16816(o[2*nj+1], al, vh4[2], vh4[3]);
                mma16816(o[2*nj+1], ah, vl4[2], vl4[3]);
            }
        }
        __syncthreads();
    }

    const float inv0 = 1.f / l0, inv1 = 1.f / l1;
    const int b = bh >> 4, h = bh & 15;
    const int r = lane >> 2, t = lane & 3;
    const int sg0 = qt * 128 + wid * 16 + r;
    #pragma unroll
    for (int ni = 0; ni < 8; ni++) {
        int col = h * 64 + ni * 8 + t * 2;
        uint32_t hi, lo;
        size_t i0 = (size_t)(b * SEQ + sg0) * DMODEL + col;
        split_pack(o[ni][0] * inv0, o[ni][1] * inv0, hi, lo);
        *reinterpret_cast<uint32_t*>(&Oh[i0]) = hi;
        *reinterpret_cast<uint32_t*>(&Ol[i0]) = lo;
        size_t i1 = (size_t)(b * SEQ + sg0 + 8) * DMODEL + col;
        split_pack(o[ni][2] * inv1, o[ni][3] * inv1, hi, lo);
        *reinterpret_cast<uint32_t*>(&Oh[i1]) = hi;
        *reinterpret_cast<uint32_t*>(&Ol[i1]) = lo;
    }
}

// ---------------------------------------------------------------------------
extern "C" void kernel_launch(void* const* d_in, const int* in_sizes, int n_in,
                              void* d_out, int out_size)
{
    const float* x  = (const float*)d_in[0];
    const float* wq = (const float*)d_in[1];
    const float* wk = (const float*)d_in[2];
    const float* wv = (const float*)d_in[3];
    const float* wo = (const float*)d_in[4];
    float* out = (float*)d_out;

    __nv_bfloat16 *qh, *ql, *kh, *kl, *vh, *vl, *xh, *xl;
    __nv_bfloat16 *w0h, *w0l, *w1h, *w1l, *w2h, *w2l;
    cudaGetSymbolAddress((void**)&qh,  g_qh);
    cudaGetSymbolAddress((void**)&ql,  g_ql);
    cudaGetSymbolAddress((void**)&kh,  g_kh);
    cudaGetSymbolAddress((void**)&kl,  g_kl);
    cudaGetSymbolAddress((void**)&vh,  g_vh);
    cudaGetSymbolAddress((void**)&vl,  g_vl);
    cudaGetSymbolAddress((void**)&xh,  g_xh);
    cudaGetSymbolAddress((void**)&xl,  g_xl);
    cudaGetSymbolAddress((void**)&w0h, g_w0h);
    cudaGetSymbolAddress((void**)&w0l, g_w0l);
    cudaGetSymbolAddress((void**)&w1h, g_w1h);
    cudaGetSymbolAddress((void**)&w1l, g_w1l);
    cudaGetSymbolAddress((void**)&w2h, g_w2h);
    cudaGetSymbolAddress((void**)&w2l, g_w2l);

    cudaFuncSetAttribute(gemm_x3,    cudaFuncAttributeMaxDynamicSharedMemorySize, GEMM_SMEM);
    cudaFuncSetAttribute(flash_hmma, cudaFuncAttributeMaxDynamicSharedMemorySize, FLASH_SMEM);

    const int nx4 = NTOK * DMODEL / 4;
    const int nw4 = DMODEL * DMODEL / 4;

    split_bf16<<<nx4 / 256, 256>>>(x, xh, xl, nx4);
    split_bf16<<<nw4 / 256, 256>>>(wq, w0h, w0l, nw4);
    split_bf16<<<nw4 / 256, 256>>>(wk, w1h, w1l, nw4);
    split_bf16<<<nw4 / 256, 256>>>(wv, w2h, w2l, nw4);

    // fused QKV projections (z in {0,1,2})
    gemm_x3<<<dim3(DMODEL / 128, NTOK / 128, 3), 256, GEMM_SMEM>>>(
        xh, xl, w0h, w0l, w1h, w1l, w2h, w2l,
        nullptr, qh, ql, kh, kl, vh, vl, 1);

    flash_hmma<<<dim3(SEQ / 128, BATCH * NH), 256, FLASH_SMEM>>>(qh, ql, kh, kl, vh, vl, xh, xl);

    split_bf16<<<nw4 / 256, 256>>>(wo, w0h, w0l, nw4);
    gemm_x3<<<dim3(DMODEL / 128, NTOK / 128, 1), 256, GEMM_SMEM>>>(
        xh, xl, w0h, w0l, nullptr, nullptr, nullptr, nullptr,
        out, nullptr, nullptr, nullptr, nullptr, nullptr, nullptr, 0);
}

// round 6
// speedup vs baseline: 4.7750x; 1.4810x over previous
#include <cuda_runtime.h>
#include <cuda_fp16.h>
#include <cstdint>
#include <math.h>

#define BATCH  4
#define SEQ    2048
#define DMODEL 1024
#define NH     16
#define HD     64
#define NTOK   (BATCH*SEQ)

// ---------------- scratch (static device globals) ----------------
__device__ __align__(16) __half g_qh[(size_t)BATCH*NH*SEQ*HD];
__device__ __align__(16) __half g_ql[(size_t)BATCH*NH*SEQ*HD];
__device__ __align__(16) __half g_kh[(size_t)BATCH*NH*SEQ*HD];
__device__ __align__(16) __half g_vh[(size_t)BATCH*NH*SEQ*HD];
__device__ __align__(16) __half g_xh[(size_t)NTOK*DMODEL];
__device__ __align__(16) __half g_xl[(size_t)NTOK*DMODEL];
__device__ __align__(16) __half g_w0[(size_t)DMODEL*DMODEL];
__device__ __align__(16) __half g_w1[(size_t)DMODEL*DMODEL];
__device__ __align__(16) __half g_w2[(size_t)DMODEL*DMODEL];

__device__ __forceinline__ uint32_t smem_u32(const void* p) {
    uint32_t a;
    asm("{ .reg .u64 t; cvta.to.shared.u64 t, %1; cvt.u32.u64 %0, t; }" : "=r"(a) : "l"(p));
    return a;
}
__device__ __forceinline__ void ldsm4(uint32_t* r, uint32_t addr) {
    asm volatile("ldmatrix.sync.aligned.m8n8.x4.shared.b16 {%0,%1,%2,%3}, [%4];"
        : "=r"(r[0]), "=r"(r[1]), "=r"(r[2]), "=r"(r[3]) : "r"(addr));
}
__device__ __forceinline__ void ldsm4t(uint32_t* r, uint32_t addr) {
    asm volatile("ldmatrix.sync.aligned.m8n8.x4.trans.shared.b16 {%0,%1,%2,%3}, [%4];"
        : "=r"(r[0]), "=r"(r[1]), "=r"(r[2]), "=r"(r[3]) : "r"(addr));
}
__device__ __forceinline__ void mma16816(float* c, const uint32_t* a, uint32_t b0, uint32_t b1) {
    asm volatile("mma.sync.aligned.m16n8k16.row.col.f32.f16.f16.f32 "
        "{%0,%1,%2,%3}, {%4,%5,%6,%7}, {%8,%9}, {%0,%1,%2,%3};"
        : "+f"(c[0]), "+f"(c[1]), "+f"(c[2]), "+f"(c[3])
        : "r"(a[0]), "r"(a[1]), "r"(a[2]), "r"(a[3]), "r"(b0), "r"(b1));
}
__device__ __forceinline__ void split_pack_h(float p0, float p1, uint32_t& hi, uint32_t& lo) {
    __half h0 = __float2half_rn(p0), h1 = __float2half_rn(p1);
    __half l0 = __float2half_rn(p0 - __half2float(h0));
    __half l1 = __float2half_rn(p1 - __half2float(h1));
    __half2 H = __halves2half2(h0, h1);
    __half2 L = __halves2half2(l0, l1);
    hi = *reinterpret_cast<uint32_t*>(&H);
    lo = *reinterpret_cast<uint32_t*>(&L);
}
__device__ __forceinline__ uint32_t pack_h(float p0, float p1) {
    __half2 H = __halves2half2(__float2half_rn(p0), __float2half_rn(p1));
    return *reinterpret_cast<uint32_t*>(&H);
}

// ---------------------------------------------------------------------------
// fp32 -> fp16 hi/lo split (A-operand buffers)
// ---------------------------------------------------------------------------
__global__ void __launch_bounds__(256)
split_h(const float* __restrict__ src, __half* __restrict__ hi,
        __half* __restrict__ lo, int n4)
{
    int i = blockIdx.x * 256 + threadIdx.x;
    if (i >= n4) return;
    float4 x = reinterpret_cast<const float4*>(src)[i];
    uint32_t h0, l0, h1, l1;
    split_pack_h(x.x, x.y, h0, l0);
    split_pack_h(x.z, x.w, h1, l1);
    reinterpret_cast<uint32_t*>(hi)[2*i]   = h0;
    reinterpret_cast<uint32_t*>(hi)[2*i+1] = h1;
    reinterpret_cast<uint32_t*>(lo)[2*i]   = l0;
    reinterpret_cast<uint32_t*>(lo)[2*i+1] = l1;
}

// fp32 -> single fp16 (B-operand / weights)
__global__ void __launch_bounds__(256)
conv_h(const float* __restrict__ src, __half* __restrict__ dst, int n4)
{
    int i = blockIdx.x * 256 + threadIdx.x;
    if (i >= n4) return;
    float4 x = reinterpret_cast<const float4*>(src)[i];
    reinterpret_cast<uint32_t*>(dst)[2*i]   = pack_h(x.x, x.y);
    reinterpret_cast<uint32_t*>(dst)[2*i+1] = pack_h(x.z, x.w);
}

// ---------------------------------------------------------------------------
// 2-term split GEMM: C = (Ah + Al) @ B^T, A hi/lo fp16, B single fp16.
// CTA 128x128, BK=64, double-buffered cp.async, 48KB/stage, 2 CTAs/SM.
// qkv_mode=1: z=0 -> Q hi/lo (scaled 0.125), z=1 -> K single, z=2 -> V single,
//             all head-scattered [b,h,s,dk].
// qkv_mode=0: f32 row-major to Cf.
// ---------------------------------------------------------------------------
#define TSTAGE 49152
#define GEMM_SMEM (2*TSTAGE)
#define NKIT 16

__device__ __forceinline__ void issue_tile(const __half* __restrict__ src,
                                           int row0, int k0, uint32_t dst, int tid)
{
    #pragma unroll
    for (int j = 0; j < 4; j++) {
        int id = tid + j * 256;
        int r  = id >> 3;
        int c  = id & 7;
        uint32_t off = (uint32_t)(r * 128 + ((c ^ (r & 7)) * 16));
        const void* g = src + (size_t)(row0 + r) * DMODEL + k0 + c * 8;
        asm volatile("cp.async.cg.shared.global [%0], [%1], 16;" :: "r"(dst + off), "l"(g));
    }
}

__global__ void __launch_bounds__(256, 2)
gemm_h2(const __half* __restrict__ Ah, const __half* __restrict__ Al,
        const __half* __restrict__ B0, const __half* __restrict__ B1,
        const __half* __restrict__ B2,
        float* __restrict__ Cf,
        __half* __restrict__ Qh, __half* __restrict__ Ql,
        __half* __restrict__ Kh, __half* __restrict__ Vh,
        int qkv_mode)
{
    extern __shared__ char smem[];
    const uint32_t sb = smem_u32(smem);
    const int tid  = threadIdx.x;
    const int wid  = tid >> 5;
    const int lane = tid & 31;
    const int wm   = (wid & 3) * 32;
    const int wn   = (wid >> 2) * 64;
    const int bm0  = blockIdx.y * 128;
    const int bn0  = blockIdx.x * 128;
    const int z    = blockIdx.z;

    const __half* B = (z == 0) ? B0 : (z == 1) ? B1 : B2;

    // prologue: stage 0
    {
        issue_tile(Ah, bm0, 0, sb,         tid);
        issue_tile(Al, bm0, 0, sb + 16384, tid);
        issue_tile(B,  bn0, 0, sb + 32768, tid);
        asm volatile("cp.async.commit_group;" ::: "memory");
    }

    float acc[2][8][4] = {};

    #pragma unroll 1
    for (int it = 0; it < NKIT; it++) {
        const int cur = it & 1;
        if (it + 1 < NKIT) {
            uint32_t st = sb + (1 - cur) * TSTAGE;
            int k0 = (it + 1) * 64;
            issue_tile(Ah, bm0, k0, st,         tid);
            issue_tile(Al, bm0, k0, st + 16384, tid);
            issue_tile(B,  bn0, k0, st + 32768, tid);
            asm volatile("cp.async.commit_group;" ::: "memory");
            asm volatile("cp.async.wait_group 1;" ::: "memory");
        } else {
            asm volatile("cp.async.wait_group 0;" ::: "memory");
        }
        __syncthreads();

        const uint32_t st  = sb + cur * TSTAGE;
        const uint32_t sAh = st, sAl = st + 16384, sB = st + 32768;

        #pragma unroll
        for (int kk = 0; kk < 4; kk++) {
            uint32_t ah[2][4], al[2][4];
            #pragma unroll
            for (int mi = 0; mi < 2; mi++) {
                int row = wm + mi * 16 + (lane & 15);
                int c   = kk * 2 + (lane >> 4);
                uint32_t off = row * 128 + ((c ^ (row & 7)) * 16);
                ldsm4(ah[mi], sAh + off);
                ldsm4(al[mi], sAl + off);
            }
            uint32_t b[8][2];
            #pragma unroll
            for (int nj = 0; nj < 4; nj++) {
                int nrow = wn + nj * 16 + (lane & 7) + ((lane >> 4) & 1) * 8;
                int c    = kk * 2 + ((lane >> 3) & 1);
                uint32_t off = nrow * 128 + ((c ^ (nrow & 7)) * 16);
                uint32_t r4[4];
                ldsm4(r4, sB + off);
                b[nj*2][0] = r4[0]; b[nj*2][1] = r4[1];
                b[nj*2+1][0] = r4[2]; b[nj*2+1][1] = r4[3];
            }
            #pragma unroll
            for (int mi = 0; mi < 2; mi++)
                #pragma unroll
                for (int ni = 0; ni < 8; ni++) {
                    mma16816(acc[mi][ni], ah[mi], b[ni][0], b[ni][1]);
                    mma16816(acc[mi][ni], al[mi], b[ni][0], b[ni][1]);
                }
        }
        __syncthreads();
    }

    // epilogue
    const int g = lane >> 2;
    const int t = lane & 3;
    #pragma unroll
    for (int mi = 0; mi < 2; mi++) {
        #pragma unroll
        for (int ni = 0; ni < 8; ni++) {
            int mg = bm0 + wm + mi * 16 + g;
            int ng = bn0 + wn + ni * 8 + t * 2;
            if (qkv_mode) {
                int h  = ng >> 6, dk = ng & (HD - 1);
                int b0 = mg >> 11, s0 = mg & (SEQ - 1);
                size_t base0 = ((size_t)(b0 * NH + h) * SEQ + s0) * HD + dk;
                int mg1 = mg + 8;
                int b1 = mg1 >> 11, s1 = mg1 & (SEQ - 1);
                size_t base1 = ((size_t)(b1 * NH + h) * SEQ + s1) * HD + dk;
                if (z == 0) {
                    uint32_t hi, lo;
                    split_pack_h(acc[mi][ni][0] * 0.125f, acc[mi][ni][1] * 0.125f, hi, lo);
                    *reinterpret_cast<uint32_t*>(&Qh[base0]) = hi;
                    *reinterpret_cast<uint32_t*>(&Ql[base0]) = lo;
                    split_pack_h(acc[mi][ni][2] * 0.125f, acc[mi][ni][3] * 0.125f, hi, lo);
                    *reinterpret_cast<uint32_t*>(&Qh[base1]) = hi;
                    *reinterpret_cast<uint32_t*>(&Ql[base1]) = lo;
                } else {
                    __half* D = (z == 1) ? Kh : Vh;
                    *reinterpret_cast<uint32_t*>(&D[base0]) = pack_h(acc[mi][ni][0], acc[mi][ni][1]);
                    *reinterpret_cast<uint32_t*>(&D[base1]) = pack_h(acc[mi][ni][2], acc[mi][ni][3]);
                }
            } else {
                size_t base0 = (size_t)mg * DMODEL + ng;
                size_t base1 = (size_t)(mg + 8) * DMODEL + ng;
                *reinterpret_cast<float2*>(&Cf[base0]) = make_float2(acc[mi][ni][0], acc[mi][ni][1]);
                *reinterpret_cast<float2*>(&Cf[base1]) = make_float2(acc[mi][ni][2], acc[mi][ni][3]);
            }
        }
    }
}

// ---------------------------------------------------------------------------
// Flash attention, fp16 2-term split, causal.
// Q = hi/lo pair (pre-scaled), K,V single fp16. Br=128, Bc=64.
// Output written as fp16 hi/lo into the final-GEMM A buffers.
// ---------------------------------------------------------------------------
#define SQH 0
#define SQL 16384
#define SKV0 32768
#define KVSTG 16384
#define FLASH_SMEM (SKV0 + 2*KVSTG)   // 65536

__device__ __forceinline__ void flash_issue_kv(
    const __half* Kh, const __half* Vh, uint32_t kvb, size_t gbase, int tid)
{
    #pragma unroll
    for (int j = 0; j < 4; j++) {
        int idx = (j & 1) * 256 + tid;
        int row = idx >> 3;
        int c   = idx & 7;
        uint32_t dst = kvb + (uint32_t)(j >> 1) * 8192 + row * 128 + ((c ^ (row & 7)) * 16);
        const void* src = ((j >> 1) ? Vh : Kh) + gbase + (size_t)row * HD + c * 8;
        asm volatile("cp.async.cg.shared.global [%0], [%1], 16;" :: "r"(dst), "l"(src));
    }
    asm volatile("cp.async.commit_group;" ::: "memory");
}

__global__ void __launch_bounds__(256, 2)
flash_hmma(const __half* __restrict__ Qh, const __half* __restrict__ Ql,
           const __half* __restrict__ Kh, const __half* __restrict__ Vh,
           __half* __restrict__ Oh, __half* __restrict__ Ol)
{
    extern __shared__ char smem[];
    const uint32_t sb = smem_u32(smem);
    const int tid  = threadIdx.x;
    const int wid  = tid >> 5;
    const int lane = tid & 31;
    const int qt   = gridDim.x - 1 - blockIdx.x;
    const int bh   = blockIdx.y;
    const int nkt  = 2 * qt + 2;

    {
        size_t qbase = ((size_t)bh * SEQ + qt * 128) * HD;
        #pragma unroll
        for (int j = 0; j < 8; j++) {
            int idx = (j & 3) * 256 + tid;
            int row = idx >> 3;
            int c   = idx & 7;
            uint32_t dst = sb + (j < 4 ? SQH : SQL) + row * 128 + ((c ^ (row & 7)) * 16);
            const void* src = (j < 4 ? Qh : Ql) + qbase + (size_t)row * HD + c * 8;
            asm volatile("cp.async.cg.shared.global [%0], [%1], 16;" :: "r"(dst), "l"(src));
        }
    }
    flash_issue_kv(Kh, Vh, sb + SKV0, (size_t)bh * SEQ * HD, tid);

    float o[8][4] = {};
    float m0 = -1e30f, m1 = -1e30f, l0 = 0.f, l1 = 0.f;

    for (int kt = 0; kt < nkt; kt++) {
        if (kt + 1 < nkt) {
            flash_issue_kv(Kh, Vh, sb + SKV0 + ((kt + 1) & 1) * KVSTG,
                           ((size_t)bh * SEQ + (kt + 1) * 64) * HD, tid);
            asm volatile("cp.async.wait_group 1;" ::: "memory");
        } else {
            asm volatile("cp.async.wait_group 0;" ::: "memory");
        }
        __syncthreads();

        const uint32_t kvb = sb + SKV0 + (kt & 1) * KVSTG;

        // ---- S = (Qh + Ql) @ Kh^T ----
        float s[8][4] = {};
        #pragma unroll
        for (int kc = 0; kc < 4; kc++) {
            uint32_t qh4[4], ql4[4];
            {
                int row = wid * 16 + (lane & 15);
                int c   = kc * 2 + (lane >> 4);
                uint32_t off = row * 128 + ((c ^ (row & 7)) * 16);
                ldsm4(qh4, sb + SQH + off);
                ldsm4(ql4, sb + SQL + off);
            }
            #pragma unroll
            for (int nj = 0; nj < 4; nj++) {
                int nrow = nj * 16 + (lane & 7) + ((lane >> 4) & 1) * 8;
                int c    = kc * 2 + ((lane >> 3) & 1);
                uint32_t off = nrow * 128 + ((c ^ (nrow & 7)) * 16);
                uint32_t kh4[4];
                ldsm4(kh4, kvb + off);
                mma16816(s[2*nj],   qh4, kh4[0], kh4[1]);
                mma16816(s[2*nj],   ql4, kh4[0], kh4[1]);
                mma16816(s[2*nj+1], qh4, kh4[2], kh4[3]);
                mma16816(s[2*nj+1], ql4, kh4[2], kh4[3]);
            }
        }

        if (kt >= 2 * qt) {
            int rbase = qt * 128 + wid * 16 + (lane >> 2);
            #pragma unroll
            for (int ni = 0; ni < 8; ni++) {
                int colb = kt * 64 + ni * 8 + (lane & 3) * 2;
                if (colb     > rbase)     s[ni][0] = -1e30f;
                if (colb + 1 > rbase)     s[ni][1] = -1e30f;
                if (colb     > rbase + 8) s[ni][2] = -1e30f;
                if (colb + 1 > rbase + 8) s[ni][3] = -1e30f;
            }
        }

        float rx0 = -1e30f, rx1 = -1e30f;
        #pragma unroll
        for (int ni = 0; ni < 8; ni++) {
            rx0 = fmaxf(rx0, fmaxf(s[ni][0], s[ni][1]));
            rx1 = fmaxf(rx1, fmaxf(s[ni][2], s[ni][3]));
        }
        rx0 = fmaxf(rx0, __shfl_xor_sync(0xffffffffu, rx0, 1));
        rx0 = fmaxf(rx0, __shfl_xor_sync(0xffffffffu, rx0, 2));
        rx1 = fmaxf(rx1, __shfl_xor_sync(0xffffffffu, rx1, 1));
        rx1 = fmaxf(rx1, __shfl_xor_sync(0xffffffffu, rx1, 2));
        float mn0 = fmaxf(m0, rx0), mn1 = fmaxf(m1, rx1);
        float cor0 = __expf(m0 - mn0), cor1 = __expf(m1 - mn1);
        m0 = mn0; m1 = mn1;
        float sum0 = 0.f, sum1 = 0.f;
        #pragma unroll
        for (int ni = 0; ni < 8; ni++) {
            s[ni][0] = __expf(s[ni][0] - mn0); sum0 += s[ni][0];
            s[ni][1] = __expf(s[ni][1] - mn0); sum0 += s[ni][1];
            s[ni][2] = __expf(s[ni][2] - mn1); sum1 += s[ni][2];
            s[ni][3] = __expf(s[ni][3] - mn1); sum1 += s[ni][3];
        }
        sum0 += __shfl_xor_sync(0xffffffffu, sum0, 1);
        sum0 += __shfl_xor_sync(0xffffffffu, sum0, 2);
        sum1 += __shfl_xor_sync(0xffffffffu, sum1, 1);
        sum1 += __shfl_xor_sync(0xffffffffu, sum1, 2);
        l0 = l0 * cor0 + sum0;
        l1 = l1 * cor1 + sum1;
        #pragma unroll
        for (int ni = 0; ni < 8; ni++) {
            o[ni][0] *= cor0; o[ni][1] *= cor0;
            o[ni][2] *= cor1; o[ni][3] *= cor1;
        }

        // ---- O += (Ph + Pl) @ Vh ----
        #pragma unroll
        for (int kc = 0; kc < 4; kc++) {
            uint32_t ph[4], pl[4];
            split_pack_h(s[2*kc][0],   s[2*kc][1],   ph[0], pl[0]);
            split_pack_h(s[2*kc][2],   s[2*kc][3],   ph[1], pl[1]);
            split_pack_h(s[2*kc+1][0], s[2*kc+1][1], ph[2], pl[2]);
            split_pack_h(s[2*kc+1][2], s[2*kc+1][3], ph[3], pl[3]);
            #pragma unroll
            for (int nj = 0; nj < 4; nj++) {
                int row = kc * 16 + ((lane >> 3) & 1) * 8 + (lane & 7);
                int c   = 2 * nj + (lane >> 4);
                uint32_t off = row * 128 + ((c ^ (row & 7)) * 16);
                uint32_t vh4[4];
                ldsm4t(vh4, kvb + 8192 + off);
                mma16816(o[2*nj],   ph, vh4[0], vh4[1]);
                mma16816(o[2*nj],   pl, vh4[0], vh4[1]);
                mma16816(o[2*nj+1], ph, vh4[2], vh4[3]);
                mma16816(o[2*nj+1], pl, vh4[2], vh4[3]);
            }
        }
        __syncthreads();
    }

    const float inv0 = 1.f / l0, inv1 = 1.f / l1;
    const int b = bh >> 4, h = bh & 15;
    const int r = lane >> 2, t = lane & 3;
    const int sg0 = qt * 128 + wid * 16 + r;
    #pragma unroll
    for (int ni = 0; ni < 8; ni++) {
        int col = h * 64 + ni * 8 + t * 2;
        uint32_t hi, lo;
        size_t i0 = (size_t)(b * SEQ + sg0) * DMODEL + col;
        split_pack_h(o[ni][0] * inv0, o[ni][1] * inv0, hi, lo);
        *reinterpret_cast<uint32_t*>(&Oh[i0]) = hi;
        *reinterpret_cast<uint32_t*>(&Ol[i0]) = lo;
        size_t i1 = (size_t)(b * SEQ + sg0 + 8) * DMODEL + col;
        split_pack_h(o[ni][2] * inv1, o[ni][3] * inv1, hi, lo);
        *reinterpret_cast<uint32_t*>(&Oh[i1]) = hi;
        *reinterpret_cast<uint32_t*>(&Ol[i1]) = lo;
    }
}

// ---------------------------------------------------------------------------
extern "C" void kernel_launch(void* const* d_in, const int* in_sizes, int n_in,
                              void* d_out, int out_size)
{
    const float* x  = (const float*)d_in[0];
    const float* wq = (const float*)d_in[1];
    const float* wk = (const float*)d_in[2];
    const float* wv = (const float*)d_in[3];
    const float* wo = (const float*)d_in[4];
    float* out = (float*)d_out;

    __half *qh, *ql, *kh, *vh, *xh, *xl, *w0, *w1, *w2;
    cudaGetSymbolAddress((void**)&qh, g_qh);
    cudaGetSymbolAddress((void**)&ql, g_ql);
    cudaGetSymbolAddress((void**)&kh, g_kh);
    cudaGetSymbolAddress((void**)&vh, g_vh);
    cudaGetSymbolAddress((void**)&xh, g_xh);
    cudaGetSymbolAddress((void**)&xl, g_xl);
    cudaGetSymbolAddress((void**)&w0, g_w0);
    cudaGetSymbolAddress((void**)&w1, g_w1);
    cudaGetSymbolAddress((void**)&w2, g_w2);

    cudaFuncSetAttribute(gemm_h2,    cudaFuncAttributeMaxDynamicSharedMemorySize, GEMM_SMEM);
    cudaFuncSetAttribute(flash_hmma, cudaFuncAttributeMaxDynamicSharedMemorySize, FLASH_SMEM);

    const int nx4 = NTOK * DMODEL / 4;
    const int nw4 = DMODEL * DMODEL / 4;

    split_h<<<nx4 / 256, 256>>>(x, xh, xl, nx4);
    conv_h<<<nw4 / 256, 256>>>(wq, w0, nw4);
    conv_h<<<nw4 / 256, 256>>>(wk, w1, nw4);
    conv_h<<<nw4 / 256, 256>>>(wv, w2, nw4);

    // fused QKV projections
    gemm_h2<<<dim3(DMODEL / 128, NTOK / 128, 3), 256, GEMM_SMEM>>>(
        xh, xl, w0, w1, w2, nullptr, qh, ql, kh, vh, 1);

    flash_hmma<<<dim3(SEQ / 128, BATCH * NH), 256, FLASH_SMEM>>>(qh, ql, kh, vh, xh, xl);

    conv_h<<<nw4 / 256, 256>>>(wo, w0, nw4);
    gemm_h2<<<dim3(DMODEL / 128, NTOK / 128, 1), 256, GEMM_SMEM>>>(
        xh, xl, w0, nullptr, nullptr, out, nullptr, nullptr, nullptr, nullptr, 0);
}

// round 7
// speedup vs baseline: 5.2610x; 1.1018x over previous
#include <cuda_runtime.h>
#include <cuda_fp16.h>
#include <cstdint>
#include <math.h>

#define BATCH  4
#define SEQ    2048
#define DMODEL 1024
#define NH     16
#define HD     64
#define NTOK   (BATCH*SEQ)

// ---------------- scratch (static device globals) ----------------
__device__ __align__(16) __half g_qh[(size_t)BATCH*NH*SEQ*HD];
__device__ __align__(16) __half g_ql[(size_t)BATCH*NH*SEQ*HD];
__device__ __align__(16) __half g_kh[(size_t)BATCH*NH*SEQ*HD];
__device__ __align__(16) __half g_vh[(size_t)BATCH*NH*SEQ*HD];
__device__ __align__(16) __half g_xh[(size_t)NTOK*DMODEL];
__device__ __align__(16) __half g_xl[(size_t)NTOK*DMODEL];
__device__ __align__(16) __half g_w0[(size_t)DMODEL*DMODEL];
__device__ __align__(16) __half g_w1[(size_t)DMODEL*DMODEL];
__device__ __align__(16) __half g_w2[(size_t)DMODEL*DMODEL];
__device__ __align__(16) __half g_w3[(size_t)DMODEL*DMODEL];

__device__ __forceinline__ uint32_t smem_u32(const void* p) {
    uint32_t a;
    asm("{ .reg .u64 t; cvta.to.shared.u64 t, %1; cvt.u32.u64 %0, t; }" : "=r"(a) : "l"(p));
    return a;
}
__device__ __forceinline__ void ldsm4(uint32_t* r, uint32_t addr) {
    asm volatile("ldmatrix.sync.aligned.m8n8.x4.shared.b16 {%0,%1,%2,%3}, [%4];"
        : "=r"(r[0]), "=r"(r[1]), "=r"(r[2]), "=r"(r[3]) : "r"(addr));
}
__device__ __forceinline__ void ldsm4t(uint32_t* r, uint32_t addr) {
    asm volatile("ldmatrix.sync.aligned.m8n8.x4.trans.shared.b16 {%0,%1,%2,%3}, [%4];"
        : "=r"(r[0]), "=r"(r[1]), "=r"(r[2]), "=r"(r[3]) : "r"(addr));
}
__device__ __forceinline__ void mma16816(float* c, const uint32_t* a, uint32_t b0, uint32_t b1) {
    asm volatile("mma.sync.aligned.m16n8k16.row.col.f32.f16.f16.f32 "
        "{%0,%1,%2,%3}, {%4,%5,%6,%7}, {%8,%9}, {%0,%1,%2,%3};"
        : "+f"(c[0]), "+f"(c[1]), "+f"(c[2]), "+f"(c[3])
        : "r"(a[0]), "r"(a[1]), "r"(a[2]), "r"(a[3]), "r"(b0), "r"(b1));
}
__device__ __forceinline__ void split_pack_h(float p0, float p1, uint32_t& hi, uint32_t& lo) {
    __half h0 = __float2half_rn(p0), h1 = __float2half_rn(p1);
    __half l0 = __float2half_rn(p0 - __half2float(h0));
    __half l1 = __float2half_rn(p1 - __half2float(h1));
    __half2 H = __halves2half2(h0, h1);
    __half2 L = __halves2half2(l0, l1);
    hi = *reinterpret_cast<uint32_t*>(&H);
    lo = *reinterpret_cast<uint32_t*>(&L);
}
__device__ __forceinline__ uint32_t pack_h(float p0, float p1) {
    __half2 H = __halves2half2(__float2half_rn(p0), __float2half_rn(p1));
    return *reinterpret_cast<uint32_t*>(&H);
}

// ---------------------------------------------------------------------------
// fp32 -> fp16 hi/lo split (A-operand buffers)
// ---------------------------------------------------------------------------
__global__ void __launch_bounds__(256)
split_h(const float* __restrict__ src, __half* __restrict__ hi,
        __half* __restrict__ lo, int n4)
{
    int i = blockIdx.x * 256 + threadIdx.x;
    if (i >= n4) return;
    float4 x = reinterpret_cast<const float4*>(src)[i];
    uint32_t h0, l0, h1, l1;
    split_pack_h(x.x, x.y, h0, l0);
    split_pack_h(x.z, x.w, h1, l1);
    reinterpret_cast<uint32_t*>(hi)[2*i]   = h0;
    reinterpret_cast<uint32_t*>(hi)[2*i+1] = h1;
    reinterpret_cast<uint32_t*>(lo)[2*i]   = l0;
    reinterpret_cast<uint32_t*>(lo)[2*i+1] = l1;
}

// 4 weight tensors -> fp16 in one launch (blockIdx.y selects tensor)
__global__ void __launch_bounds__(256)
conv_h4(const float* __restrict__ s0, const float* __restrict__ s1,
        const float* __restrict__ s2, const float* __restrict__ s3,
        __half* __restrict__ d0, __half* __restrict__ d1,
        __half* __restrict__ d2, __half* __restrict__ d3, int n4)
{
    int i = blockIdx.x * 256 + threadIdx.x;
    if (i >= n4) return;
    const float* s; __half* d;
    switch (blockIdx.y) {
        case 0: s = s0; d = d0; break;
        case 1: s = s1; d = d1; break;
        case 2: s = s2; d = d2; break;
        default: s = s3; d = d3; break;
    }
    float4 x = reinterpret_cast<const float4*>(s)[i];
    reinterpret_cast<uint32_t*>(d)[2*i]   = pack_h(x.x, x.y);
    reinterpret_cast<uint32_t*>(d)[2*i+1] = pack_h(x.z, x.w);
}

// ---------------------------------------------------------------------------
// 2-term split GEMM: C = (Ah + Al) @ B^T. (unchanged from R6)
// ---------------------------------------------------------------------------
#define TSTAGE 49152
#define GEMM_SMEM (2*TSTAGE)
#define NKIT 16

__device__ __forceinline__ void issue_tile(const __half* __restrict__ src,
                                           int row0, int k0, uint32_t dst, int tid)
{
    #pragma unroll
    for (int j = 0; j < 4; j++) {
        int id = tid + j * 256;
        int r  = id >> 3;
        int c  = id & 7;
        uint32_t off = (uint32_t)(r * 128 + ((c ^ (r & 7)) * 16));
        const void* g = src + (size_t)(row0 + r) * DMODEL + k0 + c * 8;
        asm volatile("cp.async.cg.shared.global [%0], [%1], 16;" :: "r"(dst + off), "l"(g));
    }
}

__global__ void __launch_bounds__(256, 2)
gemm_h2(const __half* __restrict__ Ah, const __half* __restrict__ Al,
        const __half* __restrict__ B0, const __half* __restrict__ B1,
        const __half* __restrict__ B2,
        float* __restrict__ Cf,
        __half* __restrict__ Qh, __half* __restrict__ Ql,
        __half* __restrict__ Kh, __half* __restrict__ Vh,
        int qkv_mode)
{
    extern __shared__ char smem[];
    const uint32_t sb = smem_u32(smem);
    const int tid  = threadIdx.x;
    const int wid  = tid >> 5;
    const int lane = tid & 31;
    const int wm   = (wid & 3) * 32;
    const int wn   = (wid >> 2) * 64;
    const int bm0  = blockIdx.y * 128;
    const int bn0  = blockIdx.x * 128;
    const int z    = blockIdx.z;

    const __half* B = (z == 0) ? B0 : (z == 1) ? B1 : B2;

    {
        issue_tile(Ah, bm0, 0, sb,         tid);
        issue_tile(Al, bm0, 0, sb + 16384, tid);
        issue_tile(B,  bn0, 0, sb + 32768, tid);
        asm volatile("cp.async.commit_group;" ::: "memory");
    }

    float acc[2][8][4] = {};

    #pragma unroll 1
    for (int it = 0; it < NKIT; it++) {
        const int cur = it & 1;
        if (it + 1 < NKIT) {
            uint32_t st = sb + (1 - cur) * TSTAGE;
            int k0 = (it + 1) * 64;
            issue_tile(Ah, bm0, k0, st,         tid);
            issue_tile(Al, bm0, k0, st + 16384, tid);
            issue_tile(B,  bn0, k0, st + 32768, tid);
            asm volatile("cp.async.commit_group;" ::: "memory");
            asm volatile("cp.async.wait_group 1;" ::: "memory");
        } else {
            asm volatile("cp.async.wait_group 0;" ::: "memory");
        }
        __syncthreads();

        const uint32_t st  = sb + cur * TSTAGE;
        const uint32_t sAh = st, sAl = st + 16384, sB = st + 32768;

        #pragma unroll
        for (int kk = 0; kk < 4; kk++) {
            uint32_t ah[2][4], al[2][4];
            #pragma unroll
            for (int mi = 0; mi < 2; mi++) {
                int row = wm + mi * 16 + (lane & 15);
                int c   = kk * 2 + (lane >> 4);
                uint32_t off = row * 128 + ((c ^ (row & 7)) * 16);
                ldsm4(ah[mi], sAh + off);
                ldsm4(al[mi], sAl + off);
            }
            uint32_t b[8][2];
            #pragma unroll
            for (int nj = 0; nj < 4; nj++) {
                int nrow = wn + nj * 16 + (lane & 7) + ((lane >> 4) & 1) * 8;
                int c    = kk * 2 + ((lane >> 3) & 1);
                uint32_t off = nrow * 128 + ((c ^ (nrow & 7)) * 16);
                uint32_t r4[4];
                ldsm4(r4, sB + off);
                b[nj*2][0] = r4[0]; b[nj*2][1] = r4[1];
                b[nj*2+1][0] = r4[2]; b[nj*2+1][1] = r4[3];
            }
            #pragma unroll
            for (int mi = 0; mi < 2; mi++)
                #pragma unroll
                for (int ni = 0; ni < 8; ni++) {
                    mma16816(acc[mi][ni], ah[mi], b[ni][0], b[ni][1]);
                    mma16816(acc[mi][ni], al[mi], b[ni][0], b[ni][1]);
                }
        }
        __syncthreads();
    }

    const int g = lane >> 2;
    const int t = lane & 3;
    #pragma unroll
    for (int mi = 0; mi < 2; mi++) {
        #pragma unroll
        for (int ni = 0; ni < 8; ni++) {
            int mg = bm0 + wm + mi * 16 + g;
            int ng = bn0 + wn + ni * 8 + t * 2;
            if (qkv_mode) {
                int h  = ng >> 6, dk = ng & (HD - 1);
                int b0 = mg >> 11, s0 = mg & (SEQ - 1);
                size_t base0 = ((size_t)(b0 * NH + h) * SEQ + s0) * HD + dk;
                int mg1 = mg + 8;
                int b1 = mg1 >> 11, s1 = mg1 & (SEQ - 1);
                size_t base1 = ((size_t)(b1 * NH + h) * SEQ + s1) * HD + dk;
                if (z == 0) {
                    uint32_t hi, lo;
                    split_pack_h(acc[mi][ni][0] * 0.125f, acc[mi][ni][1] * 0.125f, hi, lo);
                    *reinterpret_cast<uint32_t*>(&Qh[base0]) = hi;
                    *reinterpret_cast<uint32_t*>(&Ql[base0]) = lo;
                    split_pack_h(acc[mi][ni][2] * 0.125f, acc[mi][ni][3] * 0.125f, hi, lo);
                    *reinterpret_cast<uint32_t*>(&Qh[base1]) = hi;
                    *reinterpret_cast<uint32_t*>(&Ql[base1]) = lo;
                } else {
                    __half* D = (z == 1) ? Kh : Vh;
                    *reinterpret_cast<uint32_t*>(&D[base0]) = pack_h(acc[mi][ni][0], acc[mi][ni][1]);
                    *reinterpret_cast<uint32_t*>(&D[base1]) = pack_h(acc[mi][ni][2], acc[mi][ni][3]);
                }
            } else {
                size_t base0 = (size_t)mg * DMODEL + ng;
                size_t base1 = (size_t)(mg + 8) * DMODEL + ng;
                *reinterpret_cast<float2*>(&Cf[base0]) = make_float2(acc[mi][ni][0], acc[mi][ni][1]);
                *reinterpret_cast<float2*>(&Cf[base1]) = make_float2(acc[mi][ni][2], acc[mi][ni][3]);
            }
        }
    }
}

// ---------------------------------------------------------------------------
// Flash attention, fp16, causal. Q hi/lo resident in REGISTERS (loaded once).
// P single fp16. K,V single fp16. Br=128, Bc=64.
// ---------------------------------------------------------------------------
#define SQH 0
#define SQL 16384
#define SKV0 32768
#define KVSTG 16384
#define FLASH_SMEM (SKV0 + 2*KVSTG)   // 65536

__device__ __forceinline__ void flash_issue_kv(
    const __half* Kh, const __half* Vh, uint32_t kvb, size_t gbase, int tid)
{
    #pragma unroll
    for (int j = 0; j < 4; j++) {
        int idx = (j & 1) * 256 + tid;
        int row = idx >> 3;
        int c   = idx & 7;
        uint32_t dst = kvb + (uint32_t)(j >> 1) * 8192 + row * 128 + ((c ^ (row & 7)) * 16);
        const void* src = ((j >> 1) ? Vh : Kh) + gbase + (size_t)row * HD + c * 8;
        asm volatile("cp.async.cg.shared.global [%0], [%1], 16;" :: "r"(dst), "l"(src));
    }
    asm volatile("cp.async.commit_group;" ::: "memory");
}

__global__ void __launch_bounds__(256, 2)
flash_hmma(const __half* __restrict__ Qh, const __half* __restrict__ Ql,
           const __half* __restrict__ Kh, const __half* __restrict__ Vh,
           __half* __restrict__ Oh, __half* __restrict__ Ol)
{
    extern __shared__ char smem[];
    const uint32_t sb = smem_u32(smem);
    const int tid  = threadIdx.x;
    const int wid  = tid >> 5;
    const int lane = tid & 31;
    const int qt   = gridDim.x - 1 - blockIdx.x;
    const int bh   = blockIdx.y;
    const int nkt  = 2 * qt + 2;

    // Q tile -> smem (group 0)
    {
        size_t qbase = ((size_t)bh * SEQ + qt * 128) * HD;
        #pragma unroll
        for (int j = 0; j < 8; j++) {
            int idx = (j & 3) * 256 + tid;
            int row = idx >> 3;
            int c   = idx & 7;
            uint32_t dst = sb + (j < 4 ? SQH : SQL) + row * 128 + ((c ^ (row & 7)) * 16);
            const void* src = (j < 4 ? Qh : Ql) + qbase + (size_t)row * HD + c * 8;
            asm volatile("cp.async.cg.shared.global [%0], [%1], 16;" :: "r"(dst), "l"(src));
        }
        asm volatile("cp.async.commit_group;" ::: "memory");
    }
    // KV stage 0 (group 1)
    flash_issue_kv(Kh, Vh, sb + SKV0, (size_t)bh * SEQ * HD, tid);

    // Wait for Q, hoist fragments into registers
    asm volatile("cp.async.wait_group 1;" ::: "memory");
    __syncthreads();
    uint32_t qhr[4][4], qlr[4][4];
    #pragma unroll
    for (int kc = 0; kc < 4; kc++) {
        int row = wid * 16 + (lane & 15);
        int c   = kc * 2 + (lane >> 4);
        uint32_t off = row * 128 + ((c ^ (row & 7)) * 16);
        ldsm4(qhr[kc], sb + SQH + off);
        ldsm4(qlr[kc], sb + SQL + off);
    }

    float o[8][4] = {};
    float m0 = -1e30f, m1 = -1e30f, l0 = 0.f, l1 = 0.f;

    for (int kt = 0; kt < nkt; kt++) {
        if (kt + 1 < nkt) {
            flash_issue_kv(Kh, Vh, sb + SKV0 + ((kt + 1) & 1) * KVSTG,
                           ((size_t)bh * SEQ + (kt + 1) * 64) * HD, tid);
            asm volatile("cp.async.wait_group 1;" ::: "memory");
        } else {
            asm volatile("cp.async.wait_group 0;" ::: "memory");
        }
        __syncthreads();

        const uint32_t kvb = sb + SKV0 + (kt & 1) * KVSTG;

        // ---- S = (Qh + Ql) @ Kh^T (Q from registers) ----
        float s[8][4] = {};
        #pragma unroll
        for (int kc = 0; kc < 4; kc++) {
            #pragma unroll
            for (int nj = 0; nj < 4; nj++) {
                int nrow = nj * 16 + (lane & 7) + ((lane >> 4) & 1) * 8;
                int c    = kc * 2 + ((lane >> 3) & 1);
                uint32_t off = nrow * 128 + ((c ^ (nrow & 7)) * 16);
                uint32_t kh4[4];
                ldsm4(kh4, kvb + off);
                mma16816(s[2*nj],   qhr[kc], kh4[0], kh4[1]);
                mma16816(s[2*nj],   qlr[kc], kh4[0], kh4[1]);
                mma16816(s[2*nj+1], qhr[kc], kh4[2], kh4[3]);
                mma16816(s[2*nj+1], qlr[kc], kh4[2], kh4[3]);
            }
        }

        if (kt >= 2 * qt) {
            int rbase = qt * 128 + wid * 16 + (lane >> 2);
            #pragma unroll
            for (int ni = 0; ni < 8; ni++) {
                int colb = kt * 64 + ni * 8 + (lane & 3) * 2;
                if (colb     > rbase)     s[ni][0] = -1e30f;
                if (colb + 1 > rbase)     s[ni][1] = -1e30f;
                if (colb     > rbase + 8) s[ni][2] = -1e30f;
                if (colb + 1 > rbase + 8) s[ni][3] = -1e30f;
            }
        }

        float rx0 = -1e30f, rx1 = -1e30f;
        #pragma unroll
        for (int ni = 0; ni < 8; ni++) {
            rx0 = fmaxf(rx0, fmaxf(s[ni][0], s[ni][1]));
            rx1 = fmaxf(rx1, fmaxf(s[ni][2], s[ni][3]));
        }
        rx0 = fmaxf(rx0, __shfl_xor_sync(0xffffffffu, rx0, 1));
        rx0 = fmaxf(rx0, __shfl_xor_sync(0xffffffffu, rx0, 2));
        rx1 = fmaxf(rx1, __shfl_xor_sync(0xffffffffu, rx1, 1));
        rx1 = fmaxf(rx1, __shfl_xor_sync(0xffffffffu, rx1, 2));
        float mn0 = fmaxf(m0, rx0), mn1 = fmaxf(m1, rx1);
        float cor0 = __expf(m0 - mn0), cor1 = __expf(m1 - mn1);
        m0 = mn0; m1 = mn1;
        float sum0 = 0.f, sum1 = 0.f;
        #pragma unroll
        for (int ni = 0; ni < 8; ni++) {
            s[ni][0] = __expf(s[ni][0] - mn0); sum0 += s[ni][0];
            s[ni][1] = __expf(s[ni][1] - mn0); sum0 += s[ni][1];
            s[ni][2] = __expf(s[ni][2] - mn1); sum1 += s[ni][2];
            s[ni][3] = __expf(s[ni][3] - mn1); sum1 += s[ni][3];
        }
        sum0 += __shfl_xor_sync(0xffffffffu, sum0, 1);
        sum0 += __shfl_xor_sync(0xffffffffu, sum0, 2);
        sum1 += __shfl_xor_sync(0xffffffffu, sum1, 1);
        sum1 += __shfl_xor_sync(0xffffffffu, sum1, 2);
        l0 = l0 * cor0 + sum0;
        l1 = l1 * cor1 + sum1;
        #pragma unroll
        for (int ni = 0; ni < 8; ni++) {
            o[ni][0] *= cor0; o[ni][1] *= cor0;
            o[ni][2] *= cor1; o[ni][3] *= cor1;
        }

        // ---- O += P @ V (P single fp16) ----
        #pragma unroll
        for (int kc = 0; kc < 4; kc++) {
            uint32_t ph[4];
            ph[0] = pack_h(s[2*kc][0],   s[2*kc][1]);
            ph[1] = pack_h(s[2*kc][2],   s[2*kc][3]);
            ph[2] = pack_h(s[2*kc+1][0], s[2*kc+1][1]);
            ph[3] = pack_h(s[2*kc+1][2], s[2*kc+1][3]);
            #pragma unroll
            for (int nj = 0; nj < 4; nj++) {
                int row = kc * 16 + ((lane >> 3) & 1) * 8 + (lane & 7);
                int c   = 2 * nj + (lane >> 4);
                uint32_t off = row * 128 + ((c ^ (row & 7)) * 16);
                uint32_t vh4[4];
                ldsm4t(vh4, kvb + 8192 + off);
                mma16816(o[2*nj],   ph, vh4[0], vh4[1]);
                mma16816(o[2*nj+1], ph, vh4[2], vh4[3]);
            }
        }
        __syncthreads();
    }

    const float inv0 = 1.f / l0, inv1 = 1.f / l1;
    const int b = bh >> 4, h = bh & 15;
    const int r = lane >> 2, t = lane & 3;
    const int sg0 = qt * 128 + wid * 16 + r;
    #pragma unroll
    for (int ni = 0; ni < 8; ni++) {
        int col = h * 64 + ni * 8 + t * 2;
        uint32_t hi, lo;
        size_t i0 = (size_t)(b * SEQ + sg0) * DMODEL + col;
        split_pack_h(o[ni][0] * inv0, o[ni][1] * inv0, hi, lo);
        *reinterpret_cast<uint32_t*>(&Oh[i0]) = hi;
        *reinterpret_cast<uint32_t*>(&Ol[i0]) = lo;
        size_t i1 = (size_t)(b * SEQ + sg0 + 8) * DMODEL + col;
        split_pack_h(o[ni][2] * inv1, o[ni][3] * inv1, hi, lo);
        *reinterpret_cast<uint32_t*>(&Oh[i1]) = hi;
        *reinterpret_cast<uint32_t*>(&Ol[i1]) = lo;
    }
}

// ---------------------------------------------------------------------------
extern "C" void kernel_launch(void* const* d_in, const int* in_sizes, int n_in,
                              void* d_out, int out_size)
{
    const float* x  = (const float*)d_in[0];
    const float* wq = (const float*)d_in[1];
    const float* wk = (const float*)d_in[2];
    const float* wv = (const float*)d_in[3];
    const float* wo = (const float*)d_in[4];
    float* out = (float*)d_out;

    __half *qh, *ql, *kh, *vh, *xh, *xl, *w0, *w1, *w2, *w3;
    cudaGetSymbolAddress((void**)&qh, g_qh);
    cudaGetSymbolAddress((void**)&ql, g_ql);
    cudaGetSymbolAddress((void**)&kh, g_kh);
    cudaGetSymbolAddress((void**)&vh, g_vh);
    cudaGetSymbolAddress((void**)&xh, g_xh);
    cudaGetSymbolAddress((void**)&xl, g_xl);
    cudaGetSymbolAddress((void**)&w0, g_w0);
    cudaGetSymbolAddress((void**)&w1, g_w1);
    cudaGetSymbolAddress((void**)&w2, g_w2);
    cudaGetSymbolAddress((void**)&w3, g_w3);

    cudaFuncSetAttribute(gemm_h2,    cudaFuncAttributeMaxDynamicSharedMemorySize, GEMM_SMEM);
    cudaFuncSetAttribute(flash_hmma, cudaFuncAttributeMaxDynamicSharedMemorySize, FLASH_SMEM);

    const int nx4 = NTOK * DMODEL / 4;
    const int nw4 = DMODEL * DMODEL / 4;

    split_h<<<nx4 / 256, 256>>>(x, xh, xl, nx4);
    conv_h4<<<dim3(nw4 / 256, 4), 256>>>(wq, wk, wv, wo, w0, w1, w2, w3, nw4);

    gemm_h2<<<dim3(DMODEL / 128, NTOK / 128, 3), 256, GEMM_SMEM>>>(
        xh, xl, w0, w1, w2, nullptr, qh, ql, kh, vh, 1);

    flash_hmma<<<dim3(SEQ / 128, BATCH * NH), 256, FLASH_SMEM>>>(qh, ql, kh, vh, xh, xl);

    gemm_h2<<<dim3(DMODEL / 128, NTOK / 128, 1), 256, GEMM_SMEM>>>(
        xh, xl, w3, nullptr, nullptr, out, nullptr, nullptr, nullptr, nullptr, 0);
}

// round 8
// speedup vs baseline: 7.3935x; 1.4053x over previous
#include <cuda_runtime.h>
#include <cuda_fp16.h>
#include <cstdint>
#include <math.h>

#define BATCH  4
#define SEQ    2048
#define DMODEL 1024
#define NH     16
#define HD     64
#define NTOK   (BATCH*SEQ)

// log2(e) * 1/sqrt(64): Q pre-scale so softmax can use ex2 directly
#define SCALEQ 0.18033688f

// ---------------- scratch (static device globals) ----------------
__device__ __align__(16) __half g_qh[(size_t)BATCH*NH*SEQ*HD];
__device__ __align__(16) __half g_ql[(size_t)BATCH*NH*SEQ*HD];
__device__ __align__(16) __half g_kh[(size_t)BATCH*NH*SEQ*HD];
__device__ __align__(16) __half g_vh[(size_t)BATCH*NH*SEQ*HD];
__device__ __align__(16) __half g_xh[(size_t)NTOK*DMODEL];   // x fp16, then attn fp16
__device__ __align__(16) __half g_w0[(size_t)DMODEL*DMODEL];
__device__ __align__(16) __half g_w1[(size_t)DMODEL*DMODEL];
__device__ __align__(16) __half g_w2[(size_t)DMODEL*DMODEL];
__device__ __align__(16) __half g_w3[(size_t)DMODEL*DMODEL];

__device__ __forceinline__ uint32_t smem_u32(const void* p) {
    uint32_t a;
    asm("{ .reg .u64 t; cvta.to.shared.u64 t, %1; cvt.u32.u64 %0, t; }" : "=r"(a) : "l"(p));
    return a;
}
__device__ __forceinline__ void ldsm4(uint32_t* r, uint32_t addr) {
    asm volatile("ldmatrix.sync.aligned.m8n8.x4.shared.b16 {%0,%1,%2,%3}, [%4];"
        : "=r"(r[0]), "=r"(r[1]), "=r"(r[2]), "=r"(r[3]) : "r"(addr));
}
__device__ __forceinline__ void ldsm4t(uint32_t* r, uint32_t addr) {
    asm volatile("ldmatrix.sync.aligned.m8n8.x4.trans.shared.b16 {%0,%1,%2,%3}, [%4];"
        : "=r"(r[0]), "=r"(r[1]), "=r"(r[2]), "=r"(r[3]) : "r"(addr));
}
__device__ __forceinline__ void mma16816(float* c, const uint32_t* a, uint32_t b0, uint32_t b1) {
    asm volatile("mma.sync.aligned.m16n8k16.row.col.f32.f16.f16.f32 "
        "{%0,%1,%2,%3}, {%4,%5,%6,%7}, {%8,%9}, {%0,%1,%2,%3};"
        : "+f"(c[0]), "+f"(c[1]), "+f"(c[2]), "+f"(c[3])
        : "r"(a[0]), "r"(a[1]), "r"(a[2]), "r"(a[3]), "r"(b0), "r"(b1));
}
__device__ __forceinline__ void split_pack_h(float p0, float p1, uint32_t& hi, uint32_t& lo) {
    __half h0 = __float2half_rn(p0), h1 = __float2half_rn(p1);
    __half l0 = __float2half_rn(p0 - __half2float(h0));
    __half l1 = __float2half_rn(p1 - __half2float(h1));
    __half2 H = __halves2half2(h0, h1);
    __half2 L = __halves2half2(l0, l1);
    hi = *reinterpret_cast<uint32_t*>(&H);
    lo = *reinterpret_cast<uint32_t*>(&L);
}
__device__ __forceinline__ uint32_t pack_h(float p0, float p1) {
    __half2 H = __halves2half2(__float2half_rn(p0), __float2half_rn(p1));
    return *reinterpret_cast<uint32_t*>(&H);
}
__device__ __forceinline__ float ex2(float x) {
    float y;
    asm("ex2.approx.f32 %0, %1;" : "=f"(y) : "f"(x));
    return y;
}

// ---------------------------------------------------------------------------
// fp32 -> fp16 converts
// ---------------------------------------------------------------------------
__global__ void __launch_bounds__(256)
conv_h(const float* __restrict__ src, __half* __restrict__ dst, int n4)
{
    int i = blockIdx.x * 256 + threadIdx.x;
    if (i >= n4) return;
    float4 x = reinterpret_cast<const float4*>(src)[i];
    reinterpret_cast<uint32_t*>(dst)[2*i]   = pack_h(x.x, x.y);
    reinterpret_cast<uint32_t*>(dst)[2*i+1] = pack_h(x.z, x.w);
}

__global__ void __launch_bounds__(256)
conv_h4(const float* __restrict__ s0, const float* __restrict__ s1,
        const float* __restrict__ s2, const float* __restrict__ s3,
        __half* __restrict__ d0, __half* __restrict__ d1,
        __half* __restrict__ d2, __half* __restrict__ d3, int n4)
{
    int i = blockIdx.x * 256 + threadIdx.x;
    if (i >= n4) return;
    const float* s; __half* d;
    switch (blockIdx.y) {
        case 0: s = s0; d = d0; break;
        case 1: s = s1; d = d1; break;
        case 2: s = s2; d = d2; break;
        default: s = s3; d = d3; break;
    }
    float4 x = reinterpret_cast<const float4*>(s)[i];
    reinterpret_cast<uint32_t*>(d)[2*i]   = pack_h(x.x, x.y);
    reinterpret_cast<uint32_t*>(d)[2*i+1] = pack_h(x.z, x.w);
}

// ---------------------------------------------------------------------------
// Single-term fp16 GEMM: C = A @ B^T. CTA 128x128, BK=64, double buffer.
// QKV=true: z selects W; z=0 writes Q hi/lo (scaled SCALEQ), z=1 K, z=2 V,
//           head-scattered. QKV=false: f32 row-major.
// ---------------------------------------------------------------------------
#define TSTAGE 32768
#define GEMM_SMEM (2*TSTAGE)
#define NKIT 16

__device__ __forceinline__ void issue_tile(const __half* __restrict__ src,
                                           int row0, int k0, uint32_t dst, int tid)
{
    #pragma unroll
    for (int j = 0; j < 4; j++) {
        int id = tid + j * 256;
        int r  = id >> 3;
        int c  = id & 7;
        uint32_t off = (uint32_t)(r * 128 + ((c ^ (r & 7)) * 16));
        const void* g = src + (size_t)(row0 + r) * DMODEL + k0 + c * 8;
        asm volatile("cp.async.cg.shared.global [%0], [%1], 16;" :: "r"(dst + off), "l"(g));
    }
}

template<bool QKV>
__global__ void __launch_bounds__(256, 2)
gemm_h1(const __half* __restrict__ A,
        const __half* __restrict__ B0, const __half* __restrict__ B1,
        const __half* __restrict__ B2,
        float* __restrict__ Cf,
        __half* __restrict__ Qh, __half* __restrict__ Ql,
        __half* __restrict__ Kh, __half* __restrict__ Vh)
{
    extern __shared__ char smem[];
    const uint32_t sb = smem_u32(smem);
    const int tid  = threadIdx.x;
    const int wid  = tid >> 5;
    const int lane = tid & 31;
    const int wm   = (wid & 3) * 32;
    const int wn   = (wid >> 2) * 64;
    const int bm0  = blockIdx.y * 128;
    const int bn0  = blockIdx.x * 128;
    const int z    = QKV ? blockIdx.z : 0;

    const __half* B = (z == 0) ? B0 : (z == 1) ? B1 : B2;

    {
        issue_tile(A, bm0, 0, sb,         tid);
        issue_tile(B, bn0, 0, sb + 16384, tid);
        asm volatile("cp.async.commit_group;" ::: "memory");
    }

    float acc[2][8][4] = {};

    #pragma unroll 1
    for (int it = 0; it < NKIT; it++) {
        const int cur = it & 1;
        if (it + 1 < NKIT) {
            uint32_t st = sb + (1 - cur) * TSTAGE;
            int k0 = (it + 1) * 64;
            issue_tile(A, bm0, k0, st,         tid);
            issue_tile(B, bn0, k0, st + 16384, tid);
            asm volatile("cp.async.commit_group;" ::: "memory");
            asm volatile("cp.async.wait_group 1;" ::: "memory");
        } else {
            asm volatile("cp.async.wait_group 0;" ::: "memory");
        }
        __syncthreads();

        const uint32_t sA = sb + cur * TSTAGE;
        const uint32_t sB = sA + 16384;

        #pragma unroll
        for (int kk = 0; kk < 4; kk++) {
            uint32_t a[2][4];
            #pragma unroll
            for (int mi = 0; mi < 2; mi++) {
                int row = wm + mi * 16 + (lane & 15);
                int c   = kk * 2 + (lane >> 4);
                ldsm4(a[mi], sA + row * 128 + ((c ^ (row & 7)) * 16));
            }
            uint32_t b[8][2];
            #pragma unroll
            for (int nj = 0; nj < 4; nj++) {
                int nrow = wn + nj * 16 + (lane & 7) + ((lane >> 4) & 1) * 8;
                int c    = kk * 2 + ((lane >> 3) & 1);
                uint32_t r4[4];
                ldsm4(r4, sB + nrow * 128 + ((c ^ (nrow & 7)) * 16));
                b[nj*2][0] = r4[0]; b[nj*2][1] = r4[1];
                b[nj*2+1][0] = r4[2]; b[nj*2+1][1] = r4[3];
            }
            #pragma unroll
            for (int mi = 0; mi < 2; mi++)
                #pragma unroll
                for (int ni = 0; ni < 8; ni++)
                    mma16816(acc[mi][ni], a[mi], b[ni][0], b[ni][1]);
        }
        __syncthreads();
    }

    const int g = lane >> 2;
    const int t = lane & 3;
    #pragma unroll
    for (int mi = 0; mi < 2; mi++) {
        #pragma unroll
        for (int ni = 0; ni < 8; ni++) {
            int mg = bm0 + wm + mi * 16 + g;
            int ng = bn0 + wn + ni * 8 + t * 2;
            if (QKV) {
                int h  = ng >> 6, dk = ng & (HD - 1);
                int b0 = mg >> 11, s0 = mg & (SEQ - 1);
                size_t base0 = ((size_t)(b0 * NH + h) * SEQ + s0) * HD + dk;
                int mg1 = mg + 8;
                int b1 = mg1 >> 11, s1 = mg1 & (SEQ - 1);
                size_t base1 = ((size_t)(b1 * NH + h) * SEQ + s1) * HD + dk;
                if (z == 0) {
                    uint32_t hi, lo;
                    split_pack_h(acc[mi][ni][0] * SCALEQ, acc[mi][ni][1] * SCALEQ, hi, lo);
                    *reinterpret_cast<uint32_t*>(&Qh[base0]) = hi;
                    *reinterpret_cast<uint32_t*>(&Ql[base0]) = lo;
                    split_pack_h(acc[mi][ni][2] * SCALEQ, acc[mi][ni][3] * SCALEQ, hi, lo);
                    *reinterpret_cast<uint32_t*>(&Qh[base1]) = hi;
                    *reinterpret_cast<uint32_t*>(&Ql[base1]) = lo;
                } else {
                    __half* D = (z == 1) ? Kh : Vh;
                    *reinterpret_cast<uint32_t*>(&D[base0]) = pack_h(acc[mi][ni][0], acc[mi][ni][1]);
                    *reinterpret_cast<uint32_t*>(&D[base1]) = pack_h(acc[mi][ni][2], acc[mi][ni][3]);
                }
            } else {
                size_t base0 = (size_t)mg * DMODEL + ng;
                size_t base1 = (size_t)(mg + 8) * DMODEL + ng;
                *reinterpret_cast<float2*>(&Cf[base0]) = make_float2(acc[mi][ni][0], acc[mi][ni][1]);
                *reinterpret_cast<float2*>(&Cf[base1]) = make_float2(acc[mi][ni][2], acc[mi][ni][3]);
            }
        }
    }
}

// ---------------------------------------------------------------------------
// Flash attention, fp16, causal. Q hi/lo in registers, K/V/P single fp16.
// Softmax in log2 domain (Q pre-scaled by log2e/8, ex2.approx).
// Output: single fp16 into the out-GEMM A buffer.
// ---------------------------------------------------------------------------
#define SQH 0
#define SQL 16384
#define SKV0 32768
#define KVSTG 16384
#define FLASH_SMEM (SKV0 + 2*KVSTG)   // 65536

__device__ __forceinline__ void flash_issue_kv(
    const __half* Kh, const __half* Vh, uint32_t kvb, size_t gbase, int tid)
{
    #pragma unroll
    for (int j = 0; j < 4; j++) {
        int idx = (j & 1) * 256 + tid;
        int row = idx >> 3;
        int c   = idx & 7;
        uint32_t dst = kvb + (uint32_t)(j >> 1) * 8192 + row * 128 + ((c ^ (row & 7)) * 16);
        const void* src = ((j >> 1) ? Vh : Kh) + gbase + (size_t)row * HD + c * 8;
        asm volatile("cp.async.cg.shared.global [%0], [%1], 16;" :: "r"(dst), "l"(src));
    }
    asm volatile("cp.async.commit_group;" ::: "memory");
}

__global__ void __launch_bounds__(256, 2)
flash_hmma(const __half* __restrict__ Qh, const __half* __restrict__ Ql,
           const __half* __restrict__ Kh, const __half* __restrict__ Vh,
           __half* __restrict__ Oh)
{
    extern __shared__ char smem[];
    const uint32_t sb = smem_u32(smem);
    const int tid  = threadIdx.x;
    const int wid  = tid >> 5;
    const int lane = tid & 31;
    const int qt   = gridDim.x - 1 - blockIdx.x;
    const int bh   = blockIdx.y;
    const int nkt  = 2 * qt + 2;

    {
        size_t qbase = ((size_t)bh * SEQ + qt * 128) * HD;
        #pragma unroll
        for (int j = 0; j < 8; j++) {
            int idx = (j & 3) * 256 + tid;
            int row = idx >> 3;
            int c   = idx & 7;
            uint32_t dst = sb + (j < 4 ? SQH : SQL) + row * 128 + ((c ^ (row & 7)) * 16);
            const void* src = (j < 4 ? Qh : Ql) + qbase + (size_t)row * HD + c * 8;
            asm volatile("cp.async.cg.shared.global [%0], [%1], 16;" :: "r"(dst), "l"(src));
        }
        asm volatile("cp.async.commit_group;" ::: "memory");
    }
    flash_issue_kv(Kh, Vh, sb + SKV0, (size_t)bh * SEQ * HD, tid);

    asm volatile("cp.async.wait_group 1;" ::: "memory");
    __syncthreads();
    uint32_t qhr[4][4], qlr[4][4];
    #pragma unroll
    for (int kc = 0; kc < 4; kc++) {
        int row = wid * 16 + (lane & 15);
        int c   = kc * 2 + (lane >> 4);
        uint32_t off = row * 128 + ((c ^ (row & 7)) * 16);
        ldsm4(qhr[kc], sb + SQH + off);
        ldsm4(qlr[kc], sb + SQL + off);
    }

    float o[8][4] = {};
    float m0 = -1e30f, m1 = -1e30f, l0 = 0.f, l1 = 0.f;

    for (int kt = 0; kt < nkt; kt++) {
        if (kt + 1 < nkt) {
            flash_issue_kv(Kh, Vh, sb + SKV0 + ((kt + 1) & 1) * KVSTG,
                           ((size_t)bh * SEQ + (kt + 1) * 64) * HD, tid);
            asm volatile("cp.async.wait_group 1;" ::: "memory");
        } else {
            asm volatile("cp.async.wait_group 0;" ::: "memory");
        }
        __syncthreads();

        const uint32_t kvb = sb + SKV0 + (kt & 1) * KVSTG;

        float s[8][4] = {};
        #pragma unroll
        for (int kc = 0; kc < 4; kc++) {
            #pragma unroll
            for (int nj = 0; nj < 4; nj++) {
                int nrow = nj * 16 + (lane & 7) + ((lane >> 4) & 1) * 8;
                int c    = kc * 2 + ((lane >> 3) & 1);
                uint32_t off = nrow * 128 + ((c ^ (nrow & 7)) * 16);
                uint32_t kh4[4];
                ldsm4(kh4, kvb + off);
                mma16816(s[2*nj],   qhr[kc], kh4[0], kh4[1]);
                mma16816(s[2*nj],   qlr[kc], kh4[0], kh4[1]);
                mma16816(s[2*nj+1], qhr[kc], kh4[2], kh4[3]);
                mma16816(s[2*nj+1], qlr[kc], kh4[2], kh4[3]);
            }
        }

        if (kt >= 2 * qt) {
            int rbase = qt * 128 + wid * 16 + (lane >> 2);
            #pragma unroll
            for (int ni = 0; ni < 8; ni++) {
                int colb = kt * 64 + ni * 8 + (lane & 3) * 2;
                if (colb     > rbase)     s[ni][0] = -1e30f;
                if (colb + 1 > rbase)     s[ni][1] = -1e30f;
                if (colb     > rbase + 8) s[ni][2] = -1e30f;
                if (colb + 1 > rbase + 8) s[ni][3] = -1e30f;
            }
        }

        float rx0 = -1e30f, rx1 = -1e30f;
        #pragma unroll
        for (int ni = 0; ni < 8; ni++) {
            rx0 = fmaxf(rx0, fmaxf(s[ni][0], s[ni][1]));
            rx1 = fmaxf(rx1, fmaxf(s[ni][2], s[ni][3]));
        }
        rx0 = fmaxf(rx0, __shfl_xor_sync(0xffffffffu, rx0, 1));
        rx0 = fmaxf(rx0, __shfl_xor_sync(0xffffffffu, rx0, 2));
        rx1 = fmaxf(rx1, __shfl_xor_sync(0xffffffffu, rx1, 1));
        rx1 = fmaxf(rx1, __shfl_xor_sync(0xffffffffu, rx1, 2));
        float mn0 = fmaxf(m0, rx0), mn1 = fmaxf(m1, rx1);
        float cor0 = ex2(m0 - mn0), cor1 = ex2(m1 - mn1);
        m0 = mn0; m1 = mn1;
        float sum0 = 0.f, sum1 = 0.f;
        #pragma unroll
        for (int ni = 0; ni < 8; ni++) {
            s[ni][0] = ex2(s[ni][0] - mn0); sum0 += s[ni][0];
            s[ni][1] = ex2(s[ni][1] - mn0); sum0 += s[ni][1];
            s[ni][2] = ex2(s[ni][2] - mn1); sum1 += s[ni][2];
            s[ni][3] = ex2(s[ni][3] - mn1); sum1 += s[ni][3];
        }
        sum0 += __shfl_xor_sync(0xffffffffu, sum0, 1);
        sum0 += __shfl_xor_sync(0xffffffffu, sum0, 2);
        sum1 += __shfl_xor_sync(0xffffffffu, sum1, 1);
        sum1 += __shfl_xor_sync(0xffffffffu, sum1, 2);
        l0 = l0 * cor0 + sum0;
        l1 = l1 * cor1 + sum1;
        #pragma unroll
        for (int ni = 0; ni < 8; ni++) {
            o[ni][0] *= cor0; o[ni][1] *= cor0;
            o[ni][2] *= cor1; o[ni][3] *= cor1;
        }

        #pragma unroll
        for (int kc = 0; kc < 4; kc++) {
            uint32_t ph[4];
            ph[0] = pack_h(s[2*kc][0],   s[2*kc][1]);
            ph[1] = pack_h(s[2*kc][2],   s[2*kc][3]);
            ph[2] = pack_h(s[2*kc+1][0], s[2*kc+1][1]);
            ph[3] = pack_h(s[2*kc+1][2], s[2*kc+1][3]);
            #pragma unroll
            for (int nj = 0; nj < 4; nj++) {
                int row = kc * 16 + ((lane >> 3) & 1) * 8 + (lane & 7);
                int c   = 2 * nj + (lane >> 4);
                uint32_t off = row * 128 + ((c ^ (row & 7)) * 16);
                uint32_t vh4[4];
                ldsm4t(vh4, kvb + 8192 + off);
                mma16816(o[2*nj],   ph, vh4[0], vh4[1]);
                mma16816(o[2*nj+1], ph, vh4[2], vh4[3]);
            }
        }
        __syncthreads();
    }

    const float inv0 = 1.f / l0, inv1 = 1.f / l1;
    const int b = bh >> 4, h = bh & 15;
    const int r = lane >> 2, t = lane & 3;
    const int sg0 = qt * 128 + wid * 16 + r;
    #pragma unroll
    for (int ni = 0; ni < 8; ni++) {
        int col = h * 64 + ni * 8 + t * 2;
        size_t i0 = (size_t)(b * SEQ + sg0) * DMODEL + col;
        *reinterpret_cast<uint32_t*>(&Oh[i0]) = pack_h(o[ni][0] * inv0, o[ni][1] * inv0);
        size_t i1 = (size_t)(b * SEQ + sg0 + 8) * DMODEL + col;
        *reinterpret_cast<uint32_t*>(&Oh[i1]) = pack_h(o[ni][2] * inv1, o[ni][3] * inv1);
    }
}

// ---------------------------------------------------------------------------
extern "C" void kernel_launch(void* const* d_in, const int* in_sizes, int n_in,
                              void* d_out, int out_size)
{
    const float* x  = (const float*)d_in[0];
    const float* wq = (const float*)d_in[1];
    const float* wk = (const float*)d_in[2];
    const float* wv = (const float*)d_in[3];
    const float* wo = (const float*)d_in[4];
    float* out = (float*)d_out;

    __half *qh, *ql, *kh, *vh, *xh, *w0, *w1, *w2, *w3;
    cudaGetSymbolAddress((void**)&qh, g_qh);
    cudaGetSymbolAddress((void**)&ql, g_ql);
    cudaGetSymbolAddress((void**)&kh, g_kh);
    cudaGetSymbolAddress((void**)&vh, g_vh);
    cudaGetSymbolAddress((void**)&xh, g_xh);
    cudaGetSymbolAddress((void**)&w0, g_w0);
    cudaGetSymbolAddress((void**)&w1, g_w1);
    cudaGetSymbolAddress((void**)&w2, g_w2);
    cudaGetSymbolAddress((void**)&w3, g_w3);

    cudaFuncSetAttribute(gemm_h1<true>,  cudaFuncAttributeMaxDynamicSharedMemorySize, GEMM_SMEM);
    cudaFuncSetAttribute(gemm_h1<false>, cudaFuncAttributeMaxDynamicSharedMemorySize, GEMM_SMEM);
    cudaFuncSetAttribute(flash_hmma,     cudaFuncAttributeMaxDynamicSharedMemorySize, FLASH_SMEM);

    const int nx4 = NTOK * DMODEL / 4;
    const int nw4 = DMODEL * DMODEL / 4;

    conv_h<<<nx4 / 256, 256>>>(x, xh, nx4);
    conv_h4<<<dim3(nw4 / 256, 4), 256>>>(wq, wk, wv, wo, w0, w1, w2, w3, nw4);

    gemm_h1<true><<<dim3(DMODEL / 128, NTOK / 128, 3), 256, GEMM_SMEM>>>(
        xh, w0, w1, w2, nullptr, qh, ql, kh, vh);

    flash_hmma<<<dim3(SEQ / 128, BATCH * NH), 256, FLASH_SMEM>>>(qh, ql, kh, vh, xh);

    gemm_h1<false><<<dim3(DMODEL / 128, NTOK / 128, 1), 256, GEMM_SMEM>>>(
        xh, w3, nullptr, nullptr, out, nullptr, nullptr, nullptr, nullptr);
}

// round 9
// speedup vs baseline: 8.4085x; 1.1373x over previous
#include <cuda_runtime.h>
#include <cuda_fp16.h>
#include <cstdint>
#include <math.h>

#define BATCH  4
#define SEQ    2048
#define DMODEL 1024
#define NH     16
#define HD     64
#define NTOK   (BATCH*SEQ)

// log2(e) / sqrt(64): Q pre-scale so softmax uses ex2 directly
#define SCALEQ 0.18033688f

// ---------------- scratch (static device globals) ----------------
__device__ __align__(16) __half g_qh[(size_t)BATCH*NH*SEQ*HD];
__device__ __align__(16) __half g_kh[(size_t)BATCH*NH*SEQ*HD];
__device__ __align__(16) __half g_vh[(size_t)BATCH*NH*SEQ*HD];
__device__ __align__(16) __half g_xh[(size_t)NTOK*DMODEL];   // x fp16, then attn fp16
__device__ __align__(16) __half g_w0[(size_t)DMODEL*DMODEL];
__device__ __align__(16) __half g_w1[(size_t)DMODEL*DMODEL];
__device__ __align__(16) __half g_w2[(size_t)DMODEL*DMODEL];
__device__ __align__(16) __half g_w3[(size_t)DMODEL*DMODEL];

__device__ __forceinline__ uint32_t smem_u32(const void* p) {
    uint32_t a;
    asm("{ .reg .u64 t; cvta.to.shared.u64 t, %1; cvt.u32.u64 %0, t; }" : "=r"(a) : "l"(p));
    return a;
}
__device__ __forceinline__ void ldsm4(uint32_t* r, uint32_t addr) {
    asm volatile("ldmatrix.sync.aligned.m8n8.x4.shared.b16 {%0,%1,%2,%3}, [%4];"
        : "=r"(r[0]), "=r"(r[1]), "=r"(r[2]), "=r"(r[3]) : "r"(addr));
}
__device__ __forceinline__ void ldsm4t(uint32_t* r, uint32_t addr) {
    asm volatile("ldmatrix.sync.aligned.m8n8.x4.trans.shared.b16 {%0,%1,%2,%3}, [%4];"
        : "=r"(r[0]), "=r"(r[1]), "=r"(r[2]), "=r"(r[3]) : "r"(addr));
}
__device__ __forceinline__ void mma16816(float* c, const uint32_t* a, uint32_t b0, uint32_t b1) {
    asm volatile("mma.sync.aligned.m16n8k16.row.col.f32.f16.f16.f32 "
        "{%0,%1,%2,%3}, {%4,%5,%6,%7}, {%8,%9}, {%0,%1,%2,%3};"
        : "+f"(c[0]), "+f"(c[1]), "+f"(c[2]), "+f"(c[3])
        : "r"(a[0]), "r"(a[1]), "r"(a[2]), "r"(a[3]), "r"(b0), "r"(b1));
}
__device__ __forceinline__ uint32_t pack_h(float p0, float p1) {
    __half2 H = __halves2half2(__float2half_rn(p0), __float2half_rn(p1));
    return *reinterpret_cast<uint32_t*>(&H);
}
__device__ __forceinline__ float ex2(float x) {
    float y;
    asm("ex2.approx.f32 %0, %1;" : "=f"(y) : "f"(x));
    return y;
}

// ---------------------------------------------------------------------------
// fp32 -> fp16 converts
// ---------------------------------------------------------------------------
__global__ void __launch_bounds__(256)
conv_h(const float* __restrict__ src, __half* __restrict__ dst, int n4)
{
    int i = blockIdx.x * 256 + threadIdx.x;
    if (i >= n4) return;
    float4 x = reinterpret_cast<const float4*>(src)[i];
    reinterpret_cast<uint32_t*>(dst)[2*i]   = pack_h(x.x, x.y);
    reinterpret_cast<uint32_t*>(dst)[2*i+1] = pack_h(x.z, x.w);
}

__global__ void __launch_bounds__(256)
conv_h4(const float* __restrict__ s0, const float* __restrict__ s1,
        const float* __restrict__ s2, const float* __restrict__ s3,
        __half* __restrict__ d0, __half* __restrict__ d1,
        __half* __restrict__ d2, __half* __restrict__ d3, int n4)
{
    int i = blockIdx.x * 256 + threadIdx.x;
    if (i >= n4) return;
    const float* s; __half* d;
    switch (blockIdx.y) {
        case 0: s = s0; d = d0; break;
        case 1: s = s1; d = d1; break;
        case 2: s = s2; d = d2; break;
        default: s = s3; d = d3; break;
    }
    float4 x = reinterpret_cast<const float4*>(s)[i];
    reinterpret_cast<uint32_t*>(d)[2*i]   = pack_h(x.x, x.y);
    reinterpret_cast<uint32_t*>(d)[2*i+1] = pack_h(x.z, x.w);
}

// ---------------------------------------------------------------------------
// Single-term fp16 GEMM: C = A @ B^T. CTA 128x128, BK=64, double buffer.
// QKV=true: z selects W; z=0 Q (scaled SCALEQ), z=1 K, z=2 V, head-scattered fp16.
// QKV=false: f32 row-major.
// ---------------------------------------------------------------------------
#define TSTAGE 32768
#define GEMM_SMEM (2*TSTAGE)
#define NKIT 16

__device__ __forceinline__ void issue_tile(const __half* __restrict__ src,
                                           int row0, int k0, uint32_t dst, int tid)
{
    #pragma unroll
    for (int j = 0; j < 4; j++) {
        int id = tid + j * 256;
        int r  = id >> 3;
        int c  = id & 7;
        uint32_t off = (uint32_t)(r * 128 + ((c ^ (r & 7)) * 16));
        const void* g = src + (size_t)(row0 + r) * DMODEL + k0 + c * 8;
        asm volatile("cp.async.cg.shared.global [%0], [%1], 16;" :: "r"(dst + off), "l"(g));
    }
}

template<bool QKV>
__global__ void __launch_bounds__(256, 2)
gemm_h1(const __half* __restrict__ A,
        const __half* __restrict__ B0, const __half* __restrict__ B1,
        const __half* __restrict__ B2,
        float* __restrict__ Cf,
        __half* __restrict__ Qh, __half* __restrict__ Kh, __half* __restrict__ Vh)
{
    extern __shared__ char smem[];
    const uint32_t sb = smem_u32(smem);
    const int tid  = threadIdx.x;
    const int wid  = tid >> 5;
    const int lane = tid & 31;
    const int wm   = (wid & 3) * 32;
    const int wn   = (wid >> 2) * 64;
    const int bm0  = blockIdx.y * 128;
    const int bn0  = blockIdx.x * 128;
    const int z    = QKV ? blockIdx.z : 0;

    const __half* B = (z == 0) ? B0 : (z == 1) ? B1 : B2;

    {
        issue_tile(A, bm0, 0, sb,         tid);
        issue_tile(B, bn0, 0, sb + 16384, tid);
        asm volatile("cp.async.commit_group;" ::: "memory");
    }

    float acc[2][8][4] = {};

    #pragma unroll 1
    for (int it = 0; it < NKIT; it++) {
        const int cur = it & 1;
        if (it + 1 < NKIT) {
            uint32_t st = sb + (1 - cur) * TSTAGE;
            int k0 = (it + 1) * 64;
            issue_tile(A, bm0, k0, st,         tid);
            issue_tile(B, bn0, k0, st + 16384, tid);
            asm volatile("cp.async.commit_group;" ::: "memory");
            asm volatile("cp.async.wait_group 1;" ::: "memory");
        } else {
            asm volatile("cp.async.wait_group 0;" ::: "memory");
        }
        __syncthreads();

        const uint32_t sA = sb + cur * TSTAGE;
        const uint32_t sB = sA + 16384;

        #pragma unroll
        for (int kk = 0; kk < 4; kk++) {
            uint32_t a[2][4];
            #pragma unroll
            for (int mi = 0; mi < 2; mi++) {
                int row = wm + mi * 16 + (lane & 15);
                int c   = kk * 2 + (lane >> 4);
                ldsm4(a[mi], sA + row * 128 + ((c ^ (row & 7)) * 16));
            }
            uint32_t b[8][2];
            #pragma unroll
            for (int nj = 0; nj < 4; nj++) {
                int nrow = wn + nj * 16 + (lane & 7) + ((lane >> 4) & 1) * 8;
                int c    = kk * 2 + ((lane >> 3) & 1);
                uint32_t r4[4];
                ldsm4(r4, sB + nrow * 128 + ((c ^ (nrow & 7)) * 16));
                b[nj*2][0] = r4[0]; b[nj*2][1] = r4[1];
                b[nj*2+1][0] = r4[2]; b[nj*2+1][1] = r4[3];
            }
            #pragma unroll
            for (int mi = 0; mi < 2; mi++)
                #pragma unroll
                for (int ni = 0; ni < 8; ni++)
                    mma16816(acc[mi][ni], a[mi], b[ni][0], b[ni][1]);
        }
        __syncthreads();
    }

    const int g = lane >> 2;
    const int t = lane & 3;
    #pragma unroll
    for (int mi = 0; mi < 2; mi++) {
        #pragma unroll
        for (int ni = 0; ni < 8; ni++) {
            int mg = bm0 + wm + mi * 16 + g;
            int ng = bn0 + wn + ni * 8 + t * 2;
            if (QKV) {
                int h  = ng >> 6, dk = ng & (HD - 1);
                int b0 = mg >> 11, s0 = mg & (SEQ - 1);
                size_t base0 = ((size_t)(b0 * NH + h) * SEQ + s0) * HD + dk;
                int mg1 = mg + 8;
                int b1 = mg1 >> 11, s1 = mg1 & (SEQ - 1);
                size_t base1 = ((size_t)(b1 * NH + h) * SEQ + s1) * HD + dk;
                float sc = (z == 0) ? SCALEQ : 1.0f;
                __half* D = (z == 0) ? Qh : (z == 1) ? Kh : Vh;
                *reinterpret_cast<uint32_t*>(&D[base0]) = pack_h(acc[mi][ni][0] * sc, acc[mi][ni][1] * sc);
                *reinterpret_cast<uint32_t*>(&D[base1]) = pack_h(acc[mi][ni][2] * sc, acc[mi][ni][3] * sc);
            } else {
                size_t base0 = (size_t)mg * DMODEL + ng;
                size_t base1 = (size_t)(mg + 8) * DMODEL + ng;
                *reinterpret_cast<float2*>(&Cf[base0]) = make_float2(acc[mi][ni][0], acc[mi][ni][1]);
                *reinterpret_cast<float2*>(&Cf[base1]) = make_float2(acc[mi][ni][2], acc[mi][ni][3]);
            }
        }
    }
}

// ---------------------------------------------------------------------------
// Flash attention, fp16, causal. Q single fp16 in registers; K/V/P single fp16.
// 3-stage KV cp.async ring. Softmax in log2 domain (ex2.approx).
// ---------------------------------------------------------------------------
#define SQH 0
#define SKV0 16384
#define KVSTG 16384
#define FLASH_SMEM (SKV0 + 3*KVSTG)   // 65536

__device__ __forceinline__ void flash_issue_kv(
    const __half* Kh, const __half* Vh, uint32_t kvb, size_t gbase, int tid)
{
    #pragma unroll
    for (int j = 0; j < 4; j++) {
        int idx = (j & 1) * 256 + tid;
        int row = idx >> 3;
        int c   = idx & 7;
        uint32_t dst = kvb + (uint32_t)(j >> 1) * 8192 + row * 128 + ((c ^ (row & 7)) * 16);
        const void* src = ((j >> 1) ? Vh : Kh) + gbase + (size_t)row * HD + c * 8;
        asm volatile("cp.async.cg.shared.global [%0], [%1], 16;" :: "r"(dst), "l"(src));
    }
    asm volatile("cp.async.commit_group;" ::: "memory");
}

__global__ void __launch_bounds__(256, 2)
flash_hmma(const __half* __restrict__ Qh, const __half* __restrict__ Kh,
           const __half* __restrict__ Vh, __half* __restrict__ Oh)
{
    extern __shared__ char smem[];
    const uint32_t sb = smem_u32(smem);
    const int tid  = threadIdx.x;
    const int wid  = tid >> 5;
    const int lane = tid & 31;
    const int qt   = gridDim.x - 1 - blockIdx.x;   // long CTAs first
    const int bh   = blockIdx.y;
    const int nkt  = 2 * qt + 2;
    const size_t hbase = (size_t)bh * SEQ * HD;

    // Q tile -> smem (group 0)
    {
        size_t qbase = hbase + (size_t)qt * 128 * HD;
        #pragma unroll
        for (int j = 0; j < 4; j++) {
            int idx = j * 256 + tid;
            int row = idx >> 3;
            int c   = idx & 7;
            uint32_t dst = sb + SQH + row * 128 + ((c ^ (row & 7)) * 16);
            const void* src = Qh + qbase + (size_t)row * HD + c * 8;
            asm volatile("cp.async.cg.shared.global [%0], [%1], 16;" :: "r"(dst), "l"(src));
        }
        asm volatile("cp.async.commit_group;" ::: "memory");
    }
    // KV stages 0,1 (groups 1,2) — nkt >= 2 always
    flash_issue_kv(Kh, Vh, sb + SKV0,         hbase,                tid);
    flash_issue_kv(Kh, Vh, sb + SKV0 + KVSTG, hbase + (size_t)64*HD, tid);

    // Wait for Q only (2 KV groups still pending), hoist Q fragments
    asm volatile("cp.async.wait_group 2;" ::: "memory");
    __syncthreads();
    uint32_t qhr[4][4];
    #pragma unroll
    for (int kc = 0; kc < 4; kc++) {
        int row = wid * 16 + (lane & 15);
        int c   = kc * 2 + (lane >> 4);
        ldsm4(qhr[kc], sb + SQH + row * 128 + ((c ^ (row & 7)) * 16));
    }

    float o[8][4] = {};
    float m0 = -1e30f, m1 = -1e30f, l0 = 0.f, l1 = 0.f;

    for (int kt = 0; kt < nkt; kt++) {
        if (kt + 2 < nkt) {
            flash_issue_kv(Kh, Vh, sb + SKV0 + ((kt + 2) % 3) * KVSTG,
                           hbase + (size_t)(kt + 2) * 64 * HD, tid);
            asm volatile("cp.async.wait_group 2;" ::: "memory");
        } else if (kt + 2 == nkt) {
            asm volatile("cp.async.wait_group 1;" ::: "memory");
        } else {
            asm volatile("cp.async.wait_group 0;" ::: "memory");
        }
        __syncthreads();

        const uint32_t kvb = sb + SKV0 + (kt % 3) * KVSTG;

        // ---- S = Q @ K^T (single term) ----
        float s[8][4] = {};
        #pragma unroll
        for (int kc = 0; kc < 4; kc++) {
            #pragma unroll
            for (int nj = 0; nj < 4; nj++) {
                int nrow = nj * 16 + (lane & 7) + ((lane >> 4) & 1) * 8;
                int c    = kc * 2 + ((lane >> 3) & 1);
                uint32_t kh4[4];
                ldsm4(kh4, kvb + nrow * 128 + ((c ^ (nrow & 7)) * 16));
                mma16816(s[2*nj],   qhr[kc], kh4[0], kh4[1]);
                mma16816(s[2*nj+1], qhr[kc], kh4[2], kh4[3]);
            }
        }

        // ---- causal mask (diagonal tiles only) ----
        if (kt >= 2 * qt) {
            int rbase = qt * 128 + wid * 16 + (lane >> 2);
            #pragma unroll
            for (int ni = 0; ni < 8; ni++) {
                int colb = kt * 64 + ni * 8 + (lane & 3) * 2;
                if (colb     > rbase)     s[ni][0] = -1e30f;
                if (colb + 1 > rbase)     s[ni][1] = -1e30f;
                if (colb     > rbase + 8) s[ni][2] = -1e30f;
                if (colb + 1 > rbase + 8) s[ni][3] = -1e30f;
            }
        }

        // ---- online softmax (log2 domain) ----
        float rx0 = -1e30f, rx1 = -1e30f;
        #pragma unroll
        for (int ni = 0; ni < 8; ni++) {
            rx0 = fmaxf(rx0, fmaxf(s[ni][0], s[ni][1]));
            rx1 = fmaxf(rx1, fmaxf(s[ni][2], s[ni][3]));
        }
        rx0 = fmaxf(rx0, __shfl_xor_sync(0xffffffffu, rx0, 1));
        rx0 = fmaxf(rx0, __shfl_xor_sync(0xffffffffu, rx0, 2));
        rx1 = fmaxf(rx1, __shfl_xor_sync(0xffffffffu, rx1, 1));
        rx1 = fmaxf(rx1, __shfl_xor_sync(0xffffffffu, rx1, 2));
        float mn0 = fmaxf(m0, rx0), mn1 = fmaxf(m1, rx1);
        float cor0 = ex2(m0 - mn0), cor1 = ex2(m1 - mn1);
        m0 = mn0; m1 = mn1;
        float sum0 = 0.f, sum1 = 0.f;
        #pragma unroll
        for (int ni = 0; ni < 8; ni++) {
            s[ni][0] = ex2(s[ni][0] - mn0); sum0 += s[ni][0];
            s[ni][1] = ex2(s[ni][1] - mn0); sum0 += s[ni][1];
            s[ni][2] = ex2(s[ni][2] - mn1); sum1 += s[ni][2];
            s[ni][3] = ex2(s[ni][3] - mn1); sum1 += s[ni][3];
        }
        sum0 += __shfl_xor_sync(0xffffffffu, sum0, 1);
        sum0 += __shfl_xor_sync(0xffffffffu, sum0, 2);
        sum1 += __shfl_xor_sync(0xffffffffu, sum1, 1);
        sum1 += __shfl_xor_sync(0xffffffffu, sum1, 2);
        l0 = l0 * cor0 + sum0;
        l1 = l1 * cor1 + sum1;
        #pragma unroll
        for (int ni = 0; ni < 8; ni++) {
            o[ni][0] *= cor0; o[ni][1] *= cor0;
            o[ni][2] *= cor1; o[ni][3] *= cor1;
        }

        // ---- O += P @ V (P single fp16) ----
        #pragma unroll
        for (int kc = 0; kc < 4; kc++) {
            uint32_t ph[4];
            ph[0] = pack_h(s[2*kc][0],   s[2*kc][1]);
            ph[1] = pack_h(s[2*kc][2],   s[2*kc][3]);
            ph[2] = pack_h(s[2*kc+1][0], s[2*kc+1][1]);
            ph[3] = pack_h(s[2*kc+1][2], s[2*kc+1][3]);
            #pragma unroll
            for (int nj = 0; nj < 4; nj++) {
                int row = kc * 16 + ((lane >> 3) & 1) * 8 + (lane & 7);
                int c   = 2 * nj + (lane >> 4);
                uint32_t vh4[4];
                ldsm4t(vh4, kvb + 8192 + row * 128 + ((c ^ (row & 7)) * 16));
                mma16816(o[2*nj],   ph, vh4[0], vh4[1]);
                mma16816(o[2*nj+1], ph, vh4[2], vh4[3]);
            }
        }
        __syncthreads();
    }

    // ---- epilogue: normalize, fp16, write [b, s, h*64+dk] ----
    const float inv0 = 1.f / l0, inv1 = 1.f / l1;
    const int b = bh >> 4, h = bh & 15;
    const int r = lane >> 2, t = lane & 3;
    const int sg0 = qt * 128 + wid * 16 + r;
    #pragma unroll
    for (int ni = 0; ni < 8; ni++) {
        int col = h * 64 + ni * 8 + t * 2;
        size_t i0 = (size_t)(b * SEQ + sg0) * DMODEL + col;
        *reinterpret_cast<uint32_t*>(&Oh[i0]) = pack_h(o[ni][0] * inv0, o[ni][1] * inv0);
        size_t i1 = (size_t)(b * SEQ + sg0 + 8) * DMODEL + col;
        *reinterpret_cast<uint32_t*>(&Oh[i1]) = pack_h(o[ni][2] * inv1, o[ni][3] * inv1);
    }
}

// ---------------------------------------------------------------------------
extern "C" void kernel_launch(void* const* d_in, const int* in_sizes, int n_in,
                              void* d_out, int out_size)
{
    const float* x  = (const float*)d_in[0];
    const float* wq = (const float*)d_in[1];
    const float* wk = (const float*)d_in[2];
    const float* wv = (const float*)d_in[3];
    const float* wo = (const float*)d_in[4];
    float* out = (float*)d_out;

    __half *qh, *kh, *vh, *xh, *w0, *w1, *w2, *w3;
    cudaGetSymbolAddress((void**)&qh, g_qh);
    cudaGetSymbolAddress((void**)&kh, g_kh);
    cudaGetSymbolAddress((void**)&vh, g_vh);
    cudaGetSymbolAddress((void**)&xh, g_xh);
    cudaGetSymbolAddress((void**)&w0, g_w0);
    cudaGetSymbolAddress((void**)&w1, g_w1);
    cudaGetSymbolAddress((void**)&w2, g_w2);
    cudaGetSymbolAddress((void**)&w3, g_w3);

    cudaFuncSetAttribute(gemm_h1<true>,  cudaFuncAttributeMaxDynamicSharedMemorySize, GEMM_SMEM);
    cudaFuncSetAttribute(gemm_h1<false>, cudaFuncAttributeMaxDynamicSharedMemorySize, GEMM_SMEM);
    cudaFuncSetAttribute(flash_hmma,     cudaFuncAttributeMaxDynamicSharedMemorySize, FLASH_SMEM);

    const int nx4 = NTOK * DMODEL / 4;
    const int nw4 = DMODEL * DMODEL / 4;

    conv_h<<<nx4 / 256, 256>>>(x, xh, nx4);
    conv_h4<<<dim3(nw4 / 256, 4), 256>>>(wq, wk, wv, wo, w0, w1, w2, w3, nw4);

    gemm_h1<true><<<dim3(DMODEL / 128, NTOK / 128, 3), 256, GEMM_SMEM>>>(
        xh, w0, w1, w2, nullptr, qh, kh, vh);

    flash_hmma<<<dim3(SEQ / 128, BATCH * NH), 256, FLASH_SMEM>>>(qh, kh, vh, xh);

    gemm_h1<false><<<dim3(DMODEL / 128, NTOK / 128, 1), 256, GEMM_SMEM>>>(
        xh, w3, nullptr, nullptr, out, nullptr, nullptr, nullptr);
}

// round 10
// speedup vs baseline: 8.7315x; 1.0384x over previous
#include <cuda_runtime.h>
#include <cuda_fp16.h>
#include <cstdint>
#include <math.h>

#define BATCH  4
#define SEQ    2048
#define DMODEL 1024
#define NH     16
#define HD     64
#define NTOK   (BATCH*SEQ)

// log2(e) / sqrt(64): Q pre-scale so softmax uses ex2 directly
#define SCALEQ 0.18033688f

// ---------------- scratch (static device globals) ----------------
__device__ __align__(16) __half g_qh[(size_t)BATCH*NH*SEQ*HD];
__device__ __align__(16) __half g_kh[(size_t)BATCH*NH*SEQ*HD];
__device__ __align__(16) __half g_vh[(size_t)BATCH*NH*SEQ*HD];
__device__ __align__(16) __half g_xh[(size_t)NTOK*DMODEL];   // x fp16, then attn fp16
__device__ __align__(16) __half g_w0[(size_t)DMODEL*DMODEL];
__device__ __align__(16) __half g_w1[(size_t)DMODEL*DMODEL];
__device__ __align__(16) __half g_w2[(size_t)DMODEL*DMODEL];
__device__ __align__(16) __half g_w3[(size_t)DMODEL*DMODEL];

__device__ __forceinline__ uint32_t smem_u32(const void* p) {
    uint32_t a;
    asm("{ .reg .u64 t; cvta.to.shared.u64 t, %1; cvt.u32.u64 %0, t; }" : "=r"(a) : "l"(p));
    return a;
}
__device__ __forceinline__ void ldsm4(uint32_t* r, uint32_t addr) {
    asm volatile("ldmatrix.sync.aligned.m8n8.x4.shared.b16 {%0,%1,%2,%3}, [%4];"
        : "=r"(r[0]), "=r"(r[1]), "=r"(r[2]), "=r"(r[3]) : "r"(addr));
}
__device__ __forceinline__ void ldsm4t(uint32_t* r, uint32_t addr) {
    asm volatile("ldmatrix.sync.aligned.m8n8.x4.trans.shared.b16 {%0,%1,%2,%3}, [%4];"
        : "=r"(r[0]), "=r"(r[1]), "=r"(r[2]), "=r"(r[3]) : "r"(addr));
}
__device__ __forceinline__ void mma16816(float* c, const uint32_t* a, uint32_t b0, uint32_t b1) {
    asm volatile("mma.sync.aligned.m16n8k16.row.col.f32.f16.f16.f32 "
        "{%0,%1,%2,%3}, {%4,%5,%6,%7}, {%8,%9}, {%0,%1,%2,%3};"
        : "+f"(c[0]), "+f"(c[1]), "+f"(c[2]), "+f"(c[3])
        : "r"(a[0]), "r"(a[1]), "r"(a[2]), "r"(a[3]), "r"(b0), "r"(b1));
}
__device__ __forceinline__ uint32_t pack_h(float p0, float p1) {
    __half2 H = __halves2half2(__float2half_rn(p0), __float2half_rn(p1));
    return *reinterpret_cast<uint32_t*>(&H);
}
__device__ __forceinline__ float ex2(float x) {
    float y;
    asm("ex2.approx.f32 %0, %1;" : "=f"(y) : "f"(x));
    return y;
}
__device__ __forceinline__ uint32_t ex2h2(uint32_t x) {
    uint32_t y;
    asm("ex2.approx.f16x2 %0, %1;" : "=r"(y) : "r"(x));
    return y;
}

// ---------------------------------------------------------------------------
// fp32 -> fp16 converts
// ---------------------------------------------------------------------------
__global__ void __launch_bounds__(256)
conv_h(const float* __restrict__ src, __half* __restrict__ dst, int n4)
{
    int i = blockIdx.x * 256 + threadIdx.x;
    if (i >= n4) return;
    float4 x = reinterpret_cast<const float4*>(src)[i];
    reinterpret_cast<uint32_t*>(dst)[2*i]   = pack_h(x.x, x.y);
    reinterpret_cast<uint32_t*>(dst)[2*i+1] = pack_h(x.z, x.w);
}

__global__ void __launch_bounds__(256)
conv_h4(const float* __restrict__ s0, const float* __restrict__ s1,
        const float* __restrict__ s2, const float* __restrict__ s3,
        __half* __restrict__ d0, __half* __restrict__ d1,
        __half* __restrict__ d2, __half* __restrict__ d3, int n4)
{
    int i = blockIdx.x * 256 + threadIdx.x;
    if (i >= n4) return;
    const float* s; __half* d;
    switch (blockIdx.y) {
        case 0: s = s0; d = d0; break;
        case 1: s = s1; d = d1; break;
        case 2: s = s2; d = d2; break;
        default: s = s3; d = d3; break;
    }
    float4 x = reinterpret_cast<const float4*>(s)[i];
    reinterpret_cast<uint32_t*>(d)[2*i]   = pack_h(x.x, x.y);
    reinterpret_cast<uint32_t*>(d)[2*i+1] = pack_h(x.z, x.w);
}

// ---------------------------------------------------------------------------
// Single-term fp16 GEMM: C = A @ B^T. CTA 128x128, BK=64, double buffer.
// ---------------------------------------------------------------------------
#define TSTAGE 32768
#define GEMM_SMEM (2*TSTAGE)
#define NKIT 16

__device__ __forceinline__ void issue_tile(const __half* __restrict__ src,
                                           int row0, int k0, uint32_t dst, int tid)
{
    #pragma unroll
    for (int j = 0; j < 4; j++) {
        int id = tid + j * 256;
        int r  = id >> 3;
        int c  = id & 7;
        uint32_t off = (uint32_t)(r * 128 + ((c ^ (r & 7)) * 16));
        const void* g = src + (size_t)(row0 + r) * DMODEL + k0 + c * 8;
        asm volatile("cp.async.cg.shared.global [%0], [%1], 16;" :: "r"(dst + off), "l"(g));
    }
}

template<bool QKV>
__global__ void __launch_bounds__(256, 2)
gemm_h1(const __half* __restrict__ A,
        const __half* __restrict__ B0, const __half* __restrict__ B1,
        const __half* __restrict__ B2,
        float* __restrict__ Cf,
        __half* __restrict__ Qh, __half* __restrict__ Kh, __half* __restrict__ Vh)
{
    extern __shared__ char smem[];
    const uint32_t sb = smem_u32(smem);
    const int tid  = threadIdx.x;
    const int wid  = tid >> 5;
    const int lane = tid & 31;
    const int wm   = (wid & 3) * 32;
    const int wn   = (wid >> 2) * 64;
    const int bm0  = blockIdx.y * 128;
    const int bn0  = blockIdx.x * 128;
    const int z    = QKV ? blockIdx.z : 0;

    const __half* B = (z == 0) ? B0 : (z == 1) ? B1 : B2;

    {
        issue_tile(A, bm0, 0, sb,         tid);
        issue_tile(B, bn0, 0, sb + 16384, tid);
        asm volatile("cp.async.commit_group;" ::: "memory");
    }

    float acc[2][8][4] = {};

    #pragma unroll 1
    for (int it = 0; it < NKIT; it++) {
        const int cur = it & 1;
        if (it + 1 < NKIT) {
            uint32_t st = sb + (1 - cur) * TSTAGE;
            int k0 = (it + 1) * 64;
            issue_tile(A, bm0, k0, st,         tid);
            issue_tile(B, bn0, k0, st + 16384, tid);
            asm volatile("cp.async.commit_group;" ::: "memory");
            asm volatile("cp.async.wait_group 1;" ::: "memory");
        } else {
            asm volatile("cp.async.wait_group 0;" ::: "memory");
        }
        __syncthreads();

        const uint32_t sA = sb + cur * TSTAGE;
        const uint32_t sB = sA + 16384;

        #pragma unroll
        for (int kk = 0; kk < 4; kk++) {
            uint32_t a[2][4];
            #pragma unroll
            for (int mi = 0; mi < 2; mi++) {
                int row = wm + mi * 16 + (lane & 15);
                int c   = kk * 2 + (lane >> 4);
                ldsm4(a[mi], sA + row * 128 + ((c ^ (row & 7)) * 16));
            }
            uint32_t b[8][2];
            #pragma unroll
            for (int nj = 0; nj < 4; nj++) {
                int nrow = wn + nj * 16 + (lane & 7) + ((lane >> 4) & 1) * 8;
                int c    = kk * 2 + ((lane >> 3) & 1);
                uint32_t r4[4];
                ldsm4(r4, sB + nrow * 128 + ((c ^ (nrow & 7)) * 16));
                b[nj*2][0] = r4[0]; b[nj*2][1] = r4[1];
                b[nj*2+1][0] = r4[2]; b[nj*2+1][1] = r4[3];
            }
            #pragma unroll
            for (int mi = 0; mi < 2; mi++)
                #pragma unroll
                for (int ni = 0; ni < 8; ni++)
                    mma16816(acc[mi][ni], a[mi], b[ni][0], b[ni][1]);
        }
        __syncthreads();
    }

    const int g = lane >> 2;
    const int t = lane & 3;
    #pragma unroll
    for (int mi = 0; mi < 2; mi++) {
        #pragma unroll
        for (int ni = 0; ni < 8; ni++) {
            int mg = bm0 + wm + mi * 16 + g;
            int ng = bn0 + wn + ni * 8 + t * 2;
            if (QKV) {
                int h  = ng >> 6, dk = ng & (HD - 1);
                int b0 = mg >> 11, s0 = mg & (SEQ - 1);
                size_t base0 = ((size_t)(b0 * NH + h) * SEQ + s0) * HD + dk;
                int mg1 = mg + 8;
                int b1 = mg1 >> 11, s1 = mg1 & (SEQ - 1);
                size_t base1 = ((size_t)(b1 * NH + h) * SEQ + s1) * HD + dk;
                float sc = (z == 0) ? SCALEQ : 1.0f;
                __half* D = (z == 0) ? Qh : (z == 1) ? Kh : Vh;
                *reinterpret_cast<uint32_t*>(&D[base0]) = pack_h(acc[mi][ni][0] * sc, acc[mi][ni][1] * sc);
                *reinterpret_cast<uint32_t*>(&D[base1]) = pack_h(acc[mi][ni][2] * sc, acc[mi][ni][3] * sc);
            } else {
                size_t base0 = (size_t)mg * DMODEL + ng;
                size_t base1 = (size_t)(mg + 8) * DMODEL + ng;
                *reinterpret_cast<float2*>(&Cf[base0]) = make_float2(acc[mi][ni][0], acc[mi][ni][1]);
                *reinterpret_cast<float2*>(&Cf[base1]) = make_float2(acc[mi][ni][2], acc[mi][ni][3]);
            }
        }
    }
}

// ---------------------------------------------------------------------------
// Flash attention, fp16, causal. Q single fp16 in registers; K/V/P single fp16.
// 3-stage KV ring. Softmax: ex2.approx.f16x2 + ones-MMA row sums.
// ---------------------------------------------------------------------------
#define SQH 0
#define SKV0 16384
#define KVSTG 16384
#define FLASH_SMEM (SKV0 + 3*KVSTG)   // 65536
#define ONES2 0x3C003C00u

__device__ __forceinline__ void flash_issue_kv(
    const __half* Kh, const __half* Vh, uint32_t kvb, size_t gbase, int tid)
{
    #pragma unroll
    for (int j = 0; j < 4; j++) {
        int idx = (j & 1) * 256 + tid;
        int row = idx >> 3;
        int c   = idx & 7;
        uint32_t dst = kvb + (uint32_t)(j >> 1) * 8192 + row * 128 + ((c ^ (row & 7)) * 16);
        const void* src = ((j >> 1) ? Vh : Kh) + gbase + (size_t)row * HD + c * 8;
        asm volatile("cp.async.cg.shared.global [%0], [%1], 16;" :: "r"(dst), "l"(src));
    }
    asm volatile("cp.async.commit_group;" ::: "memory");
}

__global__ void __launch_bounds__(256, 2)
flash_hmma(const __half* __restrict__ Qh, const __half* __restrict__ Kh,
           const __half* __restrict__ Vh, __half* __restrict__ Oh)
{
    extern __shared__ char smem[];
    const uint32_t sb = smem_u32(smem);
    const int tid  = threadIdx.x;
    const int wid  = tid >> 5;
    const int lane = tid & 31;
    const int qt   = gridDim.x - 1 - blockIdx.x;   // long CTAs first
    const int bh   = blockIdx.y;
    const int nkt  = 2 * qt + 2;
    const size_t hbase = (size_t)bh * SEQ * HD;

    // Q tile -> smem (group 0)
    {
        size_t qbase = hbase + (size_t)qt * 128 * HD;
        #pragma unroll
        for (int j = 0; j < 4; j++) {
            int idx = j * 256 + tid;
            int row = idx >> 3;
            int c   = idx & 7;
            uint32_t dst = sb + SQH + row * 128 + ((c ^ (row & 7)) * 16);
            const void* src = Qh + qbase + (size_t)row * HD + c * 8;
            asm volatile("cp.async.cg.shared.global [%0], [%1], 16;" :: "r"(dst), "l"(src));
        }
        asm volatile("cp.async.commit_group;" ::: "memory");
    }
    flash_issue_kv(Kh, Vh, sb + SKV0,         hbase,                 tid);
    flash_issue_kv(Kh, Vh, sb + SKV0 + KVSTG, hbase + (size_t)64*HD, tid);

    asm volatile("cp.async.wait_group 2;" ::: "memory");
    __syncthreads();
    uint32_t qhr[4][4];
    #pragma unroll
    for (int kc = 0; kc < 4; kc++) {
        int row = wid * 16 + (lane & 15);
        int c   = kc * 2 + (lane >> 4);
        ldsm4(qhr[kc], sb + SQH + row * 128 + ((c ^ (row & 7)) * 16));
    }

    float o[8][4] = {};
    float m0 = -1e30f, m1 = -1e30f, l0 = 0.f, l1 = 0.f;

    for (int kt = 0; kt < nkt; kt++) {
        if (kt + 2 < nkt) {
            flash_issue_kv(Kh, Vh, sb + SKV0 + ((kt + 2) % 3) * KVSTG,
                           hbase + (size_t)(kt + 2) * 64 * HD, tid);
            asm volatile("cp.async.wait_group 2;" ::: "memory");
        } else if (kt + 2 == nkt) {
            asm volatile("cp.async.wait_group 1;" ::: "memory");
        } else {
            asm volatile("cp.async.wait_group 0;" ::: "memory");
        }
        __syncthreads();

        const uint32_t kvb = sb + SKV0 + (kt % 3) * KVSTG;

        // ---- S = Q @ K^T ----
        float s[8][4] = {};
        #pragma unroll
        for (int kc = 0; kc < 4; kc++) {
            #pragma unroll
            for (int nj = 0; nj < 4; nj++) {
                int nrow = nj * 16 + (lane & 7) + ((lane >> 4) & 1) * 8;
                int c    = kc * 2 + ((lane >> 3) & 1);
                uint32_t kh4[4];
                ldsm4(kh4, kvb + nrow * 128 + ((c ^ (nrow & 7)) * 16));
                mma16816(s[2*nj],   qhr[kc], kh4[0], kh4[1]);
                mma16816(s[2*nj+1], qhr[kc], kh4[2], kh4[3]);
            }
        }

        // ---- causal mask (diagonal tiles only) ----
        if (kt >= 2 * qt) {
            int rbase = qt * 128 + wid * 16 + (lane >> 2);
            #pragma unroll
            for (int ni = 0; ni < 8; ni++) {
                int colb = kt * 64 + ni * 8 + (lane & 3) * 2;
                if (colb     > rbase)     s[ni][0] = -1e30f;
                if (colb + 1 > rbase)     s[ni][1] = -1e30f;
                if (colb     > rbase + 8) s[ni][2] = -1e30f;
                if (colb + 1 > rbase + 8) s[ni][3] = -1e30f;
            }
        }

        // ---- row max (fp32, quad shuffles) ----
        float rx0 = -1e30f, rx1 = -1e30f;
        #pragma unroll
        for (int ni = 0; ni < 8; ni++) {
            rx0 = fmaxf(rx0, fmaxf(s[ni][0], s[ni][1]));
            rx1 = fmaxf(rx1, fmaxf(s[ni][2], s[ni][3]));
        }
        rx0 = fmaxf(rx0, __shfl_xor_sync(0xffffffffu, rx0, 1));
        rx0 = fmaxf(rx0, __shfl_xor_sync(0xffffffffu, rx0, 2));
        rx1 = fmaxf(rx1, __shfl_xor_sync(0xffffffffu, rx1, 1));
        rx1 = fmaxf(rx1, __shfl_xor_sync(0xffffffffu, rx1, 2));
        float mn0 = fmaxf(m0, rx0), mn1 = fmaxf(m1, rx1);
        float cor0 = ex2(m0 - mn0), cor1 = ex2(m1 - mn1);
        m0 = mn0; m1 = mn1;

        // ---- P = ex2(s - m) in fp16x2 (packed A fragments) ----
        uint32_t ph[4][4];
        #pragma unroll
        for (int ni = 0; ni < 8; ni++) {
            uint32_t p01 = ex2h2(pack_h(s[ni][0] - mn0, s[ni][1] - mn0));
            uint32_t p23 = ex2h2(pack_h(s[ni][2] - mn1, s[ni][3] - mn1));
            ph[ni >> 1][(ni & 1) * 2]     = p01;
            ph[ni >> 1][(ni & 1) * 2 + 1] = p23;
        }

        // ---- rescale O ----
        #pragma unroll
        for (int ni = 0; ni < 8; ni++) {
            o[ni][0] *= cor0; o[ni][1] *= cor0;
            o[ni][2] *= cor1; o[ni][3] *= cor1;
        }

        // ---- O += P @ V ; row sums via ones-MMA ----
        float rs[4] = {};
        #pragma unroll
        for (int kc = 0; kc < 4; kc++) {
            #pragma unroll
            for (int nj = 0; nj < 4; nj++) {
                int row = kc * 16 + ((lane >> 3) & 1) * 8 + (lane & 7);
                int c   = 2 * nj + (lane >> 4);
                uint32_t vh4[4];
                ldsm4t(vh4, kvb + 8192 + row * 128 + ((c ^ (row & 7)) * 16));
                mma16816(o[2*nj],   ph[kc], vh4[0], vh4[1]);
                mma16816(o[2*nj+1], ph[kc], vh4[2], vh4[3]);
            }
            mma16816(rs, ph[kc], ONES2, ONES2);
        }
        l0 = l0 * cor0 + rs[0];
        l1 = l1 * cor1 + rs[2];
        __syncthreads();
    }

    // ---- epilogue ----
    const float inv0 = 1.f / l0, inv1 = 1.f / l1;
    const int b = bh >> 4, h = bh & 15;
    const int r = lane >> 2, t = lane & 3;
    const int sg0 = qt * 128 + wid * 16 + r;
    #pragma unroll
    for (int ni = 0; ni < 8; ni++) {
        int col = h * 64 + ni * 8 + t * 2;
        size_t i0 = (size_t)(b * SEQ + sg0) * DMODEL + col;
        *reinterpret_cast<uint32_t*>(&Oh[i0]) = pack_h(o[ni][0] * inv0, o[ni][1] * inv0);
        size_t i1 = (size_t)(b * SEQ + sg0 + 8) * DMODEL + col;
        *reinterpret_cast<uint32_t*>(&Oh[i1]) = pack_h(o[ni][2] * inv1, o[ni][3] * inv1);
    }
}

// ---------------------------------------------------------------------------
extern "C" void kernel_launch(void* const* d_in, const int* in_sizes, int n_in,
                              void* d_out, int out_size)
{
    const float* x  = (const float*)d_in[0];
    const float* wq = (const float*)d_in[1];
    const float* wk = (const float*)d_in[2];
    const float* wv = (const float*)d_in[3];
    const float* wo = (const float*)d_in[4];
    float* out = (float*)d_out;

    __half *qh, *kh, *vh, *xh, *w0, *w1, *w2, *w3;
    cudaGetSymbolAddress((void**)&qh, g_qh);
    cudaGetSymbolAddress((void**)&kh, g_kh);
    cudaGetSymbolAddress((void**)&vh, g_vh);
    cudaGetSymbolAddress((void**)&xh, g_xh);
    cudaGetSymbolAddress((void**)&w0, g_w0);
    cudaGetSymbolAddress((void**)&w1, g_w1);
    cudaGetSymbolAddress((void**)&w2, g_w2);
    cudaGetSymbolAddress((void**)&w3, g_w3);

    cudaFuncSetAttribute(gemm_h1<true>,  cudaFuncAttributeMaxDynamicSharedMemorySize, GEMM_SMEM);
    cudaFuncSetAttribute(gemm_h1<false>, cudaFuncAttributeMaxDynamicSharedMemorySize, GEMM_SMEM);
    cudaFuncSetAttribute(flash_hmma,     cudaFuncAttributeMaxDynamicSharedMemorySize, FLASH_SMEM);

    const int nx4 = NTOK * DMODEL / 4;
    const int nw4 = DMODEL * DMODEL / 4;

    conv_h<<<nx4 / 256, 256>>>(x, xh, nx4);
    conv_h4<<<dim3(nw4 / 256, 4), 256>>>(wq, wk, wv, wo, w0, w1, w2, w3, nw4);

    gemm_h1<true><<<dim3(DMODEL / 128, NTOK / 128, 3), 256, GEMM_SMEM>>>(
        xh, w0, w1, w2, nullptr, qh, kh, vh);

    flash_hmma<<<dim3(SEQ / 128, BATCH * NH), 256, FLASH_SMEM>>>(qh, kh, vh, xh);

    gemm_h1<false><<<dim3(DMODEL / 128, NTOK / 128, 1), 256, GEMM_SMEM>>>(
        xh, w3, nullptr, nullptr, out, nullptr, nullptr, nullptr);
}